// round 1
// baseline (speedup 1.0000x reference)
#include <cuda_runtime.h>
#include <cstdint>

// ---------------- problem dims ----------------
#define BSZ   2048
#define TST   100
#define EMB   200
#define SDIM  12
#define GDIM  600            // 3*EMB
#define MBIG  (TST*BSZ)      // 204800 rows (all timesteps)
#define MROWS ((TST+1)*BSZ)  // 206848 rows (hiddens)
#define EPSV  1e-4f

// ---------------- device scratch (static; no runtime alloc) ----------------
__device__ float g_h1_small[BSZ * EMB];
__device__ float g_ctx_embed[BSZ * EMB];
__device__ float g_gibase[BSZ * GDIM];                 // ctx@Wih[:, :200]^T + b_ih
__device__ float g_big_h1[(size_t)MBIG * EMB];         // reused hidden-1 buffer
__device__ float g_alc[(size_t)MBIG * 400];            // [a_embed | lc_embed]
__device__ float g_gi[(size_t)MBIG * GDIM];            // precomputed input gates
__device__ float g_hiddens[(size_t)MROWS * EMB];       // h_0 .. h_T
__device__ float g_gh[BSZ * GDIM];                     // per-step h@Whh^T
__device__ float g_tmp[(size_t)MROWS * EMB];           // decode/cov hidden layer

// ---------------- generic NT GEMM: C = act(A@W^T + bias [+ base]) ----------------
// A: [M,K] lda, W: [N,K] ldw, C: [M,N] ldc. base (optional): row (m & baseMask), ld 600.
#define TBM 128
#define TBN 64
#define TBK 16

enum { ACT_NONE = 0, ACT_RELU = 1, ACT_TANH = 2 };

template <int ACT, bool HAS_BASE>
__global__ void __launch_bounds__(256)
gemm_nt(const float* __restrict__ A, int lda,
        const float* __restrict__ W, int ldw,
        const float* __restrict__ bias,
        const float* __restrict__ base, int baseMask,
        float* __restrict__ C, int ldc,
        int M, int N, int K)
{
    __shared__ float As[TBK][TBM + 4];
    __shared__ float Ws[TBK][TBN + 4];

    const int bm  = blockIdx.y * TBM;
    const int bn  = blockIdx.x * TBN;
    const int tid = threadIdx.x;
    const int tcol = tid & 15;   // 16 cols of threads -> n
    const int trow = tid >> 4;   // 16 rows of threads -> m

    float acc[8][4];
#pragma unroll
    for (int i = 0; i < 8; i++)
#pragma unroll
        for (int j = 0; j < 4; j++) acc[i][j] = 0.f;

    for (int k0 = 0; k0 < K; k0 += TBK) {
        // A tile: 128x16 (8 elems/thread), coalesced along k
#pragma unroll
        for (int i = 0; i < 8; i++) {
            int e = tid + i * 256;
            int r = e >> 4, c = e & 15;
            int gm = bm + r, gk = k0 + c;
            float v = 0.f;
            if (gm < M && gk < K) v = A[(size_t)gm * lda + gk];
            As[c][r] = v;
        }
        // W tile: 64x16 (4 elems/thread)
#pragma unroll
        for (int i = 0; i < 4; i++) {
            int e = tid + i * 256;
            int r = e >> 4, c = e & 15;
            int gn = bn + r, gk = k0 + c;
            float v = 0.f;
            if (gn < N && gk < K) v = W[(size_t)gn * ldw + gk];
            Ws[c][r] = v;
        }
        __syncthreads();

#pragma unroll
        for (int k = 0; k < TBK; k++) {
            float4 a0 = *reinterpret_cast<const float4*>(&As[k][trow * 8]);
            float4 a1 = *reinterpret_cast<const float4*>(&As[k][trow * 8 + 4]);
            float4 w0 = *reinterpret_cast<const float4*>(&Ws[k][tcol * 4]);
            float a[8] = {a0.x, a0.y, a0.z, a0.w, a1.x, a1.y, a1.z, a1.w};
            float w[4] = {w0.x, w0.y, w0.z, w0.w};
#pragma unroll
            for (int i = 0; i < 8; i++)
#pragma unroll
                for (int j = 0; j < 4; j++)
                    acc[i][j] = fmaf(a[i], w[j], acc[i][j]);
        }
        __syncthreads();
    }

#pragma unroll
    for (int i = 0; i < 8; i++) {
        int gm = bm + trow * 8 + i;
        if (gm >= M) continue;
#pragma unroll
        for (int j = 0; j < 4; j++) {
            int gn = bn + tcol * 4 + j;
            if (gn >= N) continue;
            float v = acc[i][j];
            if (bias) v += bias[gn];
            if (HAS_BASE) v += base[(size_t)(gm & baseMask) * 600 + gn];
            if (ACT == ACT_RELU) v = fmaxf(v, 0.f);
            else if (ACT == ACT_TANH) v = tanhf(v);
            C[(size_t)gm * ldc + gn] = v;
        }
    }
}

// ---------------- tiny-K first layer: Y[m,j] = relu(X[m,:]@W[j,:] + b[j]) ----------------
__global__ void embed1_kernel(const float* __restrict__ X,
                              const float* __restrict__ W,
                              const float* __restrict__ B,
                              float* __restrict__ Y, int M, int K)
{
    int idx = blockIdx.x * blockDim.x + threadIdx.x;
    if (idx >= M * EMB) return;
    int m = idx / EMB, j = idx - m * EMB;
    const float* xr = X + (size_t)m * K;
    const float* wr = W + (size_t)j * K;
    float s = B[j];
    for (int k = 0; k < K; k++) s = fmaf(xr[k], wr[k], s);
    Y[idx] = fmaxf(s, 0.f);
}

// ---------------- GRU gate combine (per step) ----------------
__global__ void gru_gate_kernel(const float* __restrict__ gi,
                                const float* __restrict__ gh,
                                const float* __restrict__ h,
                                float* __restrict__ hnew)
{
    int idx = blockIdx.x * blockDim.x + threadIdx.x;
    if (idx >= BSZ * EMB) return;
    int b = idx / EMB, j = idx - b * EMB;
    const float* gib = gi + (size_t)b * GDIM;
    const float* ghb = gh + (size_t)b * GDIM;
    float r = 1.f / (1.f + expf(-(gib[j]       + ghb[j])));
    float z = 1.f / (1.f + expf(-(gib[j + 200] + ghb[j + 200])));
    float n = tanhf(gib[j + 400] + r * ghb[j + 400]);
    hnew[idx] = (1.f - z) * n + z * h[idx];
}

// ---------------- 200 -> 12 projection, warp per row ----------------
template <int MODE> // 0: mean (linear), 1: std (sqrt(softplus(v)+eps))
__global__ void proj_kernel(const float* __restrict__ H,
                            const float* __restrict__ W2,
                            const float* __restrict__ b2,
                            float* __restrict__ out, int M)
{
    int warp = (blockIdx.x * blockDim.x + threadIdx.x) >> 5;
    int lane = threadIdx.x & 31;
    if (warp >= M) return;
    const float* row = H + (size_t)warp * EMB;
    float acc[SDIM];
#pragma unroll
    for (int s = 0; s < SDIM; s++) acc[s] = 0.f;
    for (int k = lane; k < EMB; k += 32) {
        float hv = row[k];
#pragma unroll
        for (int s = 0; s < SDIM; s++)
            acc[s] = fmaf(hv, W2[s * EMB + k], acc[s]);
    }
#pragma unroll
    for (int s = 0; s < SDIM; s++) {
#pragma unroll
        for (int off = 16; off > 0; off >>= 1)
            acc[s] += __shfl_xor_sync(0xffffffffu, acc[s], off);
    }
    if (lane == 0) {
        float* o = out + (size_t)warp * SDIM;
#pragma unroll
        for (int s = 0; s < SDIM; s++) {
            float v = acc[s] + b2[s];
            if (MODE == 1) {
                // stable softplus: log1p(exp(-|v|)) + max(v,0)
                float sp = log1pf(expf(-fabsf(v))) + fmaxf(v, 0.f);
                v = sqrtf(sp + EPSV);
            }
            o[s] = v;
        }
    }
}

// ---------------- host-side helpers ----------------
static void launch_gemm(int act, const float* A, int lda, const float* W, int ldw,
                        const float* bias, const float* base, int baseMask,
                        float* C, int ldc, int M, int N, int K)
{
    dim3 grid((N + TBN - 1) / TBN, (M + TBM - 1) / TBM);
    dim3 blk(256);
    if (base) {
        if (act == ACT_NONE)      gemm_nt<ACT_NONE, true><<<grid, blk>>>(A, lda, W, ldw, bias, base, baseMask, C, ldc, M, N, K);
        else if (act == ACT_RELU) gemm_nt<ACT_RELU, true><<<grid, blk>>>(A, lda, W, ldw, bias, base, baseMask, C, ldc, M, N, K);
        else                      gemm_nt<ACT_TANH, true><<<grid, blk>>>(A, lda, W, ldw, bias, base, baseMask, C, ldc, M, N, K);
    } else {
        if (act == ACT_NONE)      gemm_nt<ACT_NONE, false><<<grid, blk>>>(A, lda, W, ldw, bias, nullptr, 0, C, ldc, M, N, K);
        else if (act == ACT_RELU) gemm_nt<ACT_RELU, false><<<grid, blk>>>(A, lda, W, ldw, bias, nullptr, 0, C, ldc, M, N, K);
        else                      gemm_nt<ACT_TANH, false><<<grid, blk>>>(A, lda, W, ldw, bias, nullptr, 0, C, ldc, M, N, K);
    }
}

extern "C" void kernel_launch(void* const* d_in, const int* in_sizes, int n_in,
                              void* d_out, int out_size)
{
    // inputs per metadata order
    const float* x        = (const float*)d_in[0];
    const float* u        = (const float*)d_in[1];
    const float* ctx_mean = (const float*)d_in[2];
    const float* lctx     = (const float*)d_in[3];
    const float* se_w1 = (const float*)d_in[4];  const float* se_b1 = (const float*)d_in[5];
    const float* se_w2 = (const float*)d_in[6];  const float* se_b2 = (const float*)d_in[7];
    const float* ae_w1 = (const float*)d_in[8];  const float* ae_b1 = (const float*)d_in[9];
    const float* ae_w2 = (const float*)d_in[10]; const float* ae_b2 = (const float*)d_in[11];
    const float* ce_w1 = (const float*)d_in[12]; const float* ce_b1 = (const float*)d_in[13];
    const float* ce_w2 = (const float*)d_in[14]; const float* ce_b2 = (const float*)d_in[15];
    const float* lce_w1 = (const float*)d_in[16]; const float* lce_b1 = (const float*)d_in[17];
    const float* lce_w2 = (const float*)d_in[18]; const float* lce_b2 = (const float*)d_in[19];
    const float* dec_w1 = (const float*)d_in[20]; const float* dec_b1 = (const float*)d_in[21];
    const float* dec_w2 = (const float*)d_in[22]; const float* dec_b2 = (const float*)d_in[23];
    const float* gru_wih = (const float*)d_in[24]; const float* gru_bih = (const float*)d_in[25];
    const float* gru_whh = (const float*)d_in[26]; const float* gru_bhh = (const float*)d_in[27];
    const float* cov_w1 = (const float*)d_in[28]; const float* cov_b1 = (const float*)d_in[29];
    const float* cov_w2 = (const float*)d_in[30]; const float* cov_b2 = (const float*)d_in[31];

    float *p_h1s, *p_ctx, *p_gibase, *p_bigh1, *p_alc, *p_gi, *p_hid, *p_gh, *p_tmp;
    cudaGetSymbolAddress((void**)&p_h1s,    g_h1_small);
    cudaGetSymbolAddress((void**)&p_ctx,    g_ctx_embed);
    cudaGetSymbolAddress((void**)&p_gibase, g_gibase);
    cudaGetSymbolAddress((void**)&p_bigh1,  g_big_h1);
    cudaGetSymbolAddress((void**)&p_alc,    g_alc);
    cudaGetSymbolAddress((void**)&p_gi,     g_gi);
    cudaGetSymbolAddress((void**)&p_hid,    g_hiddens);
    cudaGetSymbolAddress((void**)&p_gh,     g_gh);
    cudaGetSymbolAddress((void**)&p_tmp,    g_tmp);

    float* out_mean = (float*)d_out;
    float* out_std  = out_mean + (size_t)MROWS * SDIM;

    const int eb = 256;

    // state_embed -> hiddens row block 0
    embed1_kernel<<<(BSZ * EMB + eb - 1) / eb, eb>>>(x, se_w1, se_b1, p_h1s, BSZ, SDIM);
    launch_gemm(ACT_TANH, p_h1s, EMB, se_w2, EMB, se_b2, nullptr, 0, p_hid, EMB, BSZ, EMB, EMB);

    // ctx_embed, then gi_base = ctx_embed @ Wih[:, :200]^T + b_ih
    embed1_kernel<<<(BSZ * EMB + eb - 1) / eb, eb>>>(ctx_mean, ce_w1, ce_b1, p_h1s, BSZ, 8);
    launch_gemm(ACT_RELU, p_h1s, EMB, ce_w2, EMB, ce_b2, nullptr, 0, p_ctx, EMB, BSZ, EMB, EMB);
    launch_gemm(ACT_NONE, p_ctx, EMB, gru_wih, GDIM, gru_bih, nullptr, 0, p_gibase, GDIM, BSZ, GDIM, EMB);

    // action embed (all T) -> g_alc cols [0,200)
    embed1_kernel<<<((size_t)MBIG * EMB + eb - 1) / eb, eb>>>(u, ae_w1, ae_b1, p_bigh1, MBIG, 4);
    launch_gemm(ACT_RELU, p_bigh1, EMB, ae_w2, EMB, ae_b2, nullptr, 0, p_alc, 400, MBIG, EMB, EMB);

    // local ctx embed (all T) -> g_alc cols [200,400)
    embed1_kernel<<<((size_t)MBIG * EMB + eb - 1) / eb, eb>>>(lctx, lce_w1, lce_b1, p_bigh1, MBIG, 6);
    launch_gemm(ACT_RELU, p_bigh1, EMB, lce_w2, EMB, lce_b2, nullptr, 0, p_alc + 200, 400, MBIG, EMB, EMB);

    // gi[t,b,:] = [a|lc] @ Wih[:, 200:600]^T + gi_base[b,:]   (one big K=400 GEMM)
    launch_gemm(ACT_NONE, p_alc, 400, gru_wih + 200, GDIM, nullptr, p_gibase, BSZ - 1,
                p_gi, GDIM, MBIG, GDIM, 400);

    // sequential GRU scan
    for (int t = 0; t < TST; t++) {
        const float* h_cur = p_hid + (size_t)t * BSZ * EMB;
        float* h_nxt       = p_hid + (size_t)(t + 1) * BSZ * EMB;
        launch_gemm(ACT_NONE, h_cur, EMB, gru_whh, EMB, gru_bhh, nullptr, 0,
                    p_gh, GDIM, BSZ, GDIM, EMB);
        gru_gate_kernel<<<(BSZ * EMB + eb - 1) / eb, eb>>>(
            p_gi + (size_t)t * BSZ * GDIM, p_gh, h_cur, h_nxt);
    }

    // decode mean
    launch_gemm(ACT_RELU, p_hid, EMB, dec_w1, EMB, dec_b1, nullptr, 0, p_tmp, EMB, MROWS, EMB, EMB);
    {
        int warps = MROWS, blocks = (warps * 32 + 255) / 256;
        proj_kernel<0><<<blocks, 256>>>(p_tmp, dec_w2, dec_b2, out_mean, MROWS);
    }
    // cov -> std
    launch_gemm(ACT_RELU, p_hid, EMB, cov_w1, EMB, cov_b1, nullptr, 0, p_tmp, EMB, MROWS, EMB, EMB);
    {
        int warps = MROWS, blocks = (warps * 32 + 255) / 256;
        proj_kernel<1><<<blocks, 256>>>(p_tmp, cov_w2, cov_b2, out_std, MROWS);
    }

    (void)in_sizes; (void)n_in; (void)out_size;
}

// round 2
// speedup vs baseline: 1.3121x; 1.3121x over previous
#include <cuda_runtime.h>
#include <cstdint>

// ---------------- problem dims ----------------
#define BSZ   2048
#define TST   100
#define EMB   200
#define SDIM  12
#define GDIM  600            // 3*EMB
#define MBIG  (TST*BSZ)      // 204800 rows (all timesteps)
#define MROWS ((TST+1)*BSZ)  // 206848 rows (hiddens)
#define EPSV  1e-4f

typedef unsigned long long ull;

__device__ __forceinline__ ull ffma2(ull a, ull b, ull c) {
    ull d;
    asm("fma.rn.f32x2 %0, %1, %2, %3;" : "=l"(d) : "l"(a), "l"(b), "l"(c));
    return d;
}
__device__ __forceinline__ ull pack2(float lo, float hi) {
    ull d;
    asm("mov.b64 %0, {%1, %2};" : "=l"(d) : "f"(lo), "f"(hi));
    return d;
}
__device__ __forceinline__ float2 unpack2(ull v) {
    float2 r;
    asm("mov.b64 {%0, %1}, %2;" : "=f"(r.x), "=f"(r.y) : "l"(v));
    return r;
}

// ---------------- device scratch (static; no runtime alloc) ----------------
__device__ float g_h1_small[BSZ * EMB];
__device__ float g_ctx_embed[BSZ * EMB];
__device__ float g_gibase[BSZ * GDIM];                 // ctx@Wih[:, :200]^T + b_ih
__device__ float g_big_h1[(size_t)MBIG * EMB];         // reused hidden-1 buffer
__device__ float g_alc[(size_t)MBIG * 400];            // [a_embed | lc_embed]
__device__ float g_gi[(size_t)MBIG * GDIM];            // precomputed input gates
__device__ float g_hiddens[(size_t)MROWS * EMB];       // h_0 .. h_T
__device__ float g_tmp[(size_t)MROWS * EMB];           // decode/cov hidden layer
__device__ float g_whh_t[EMB * GDIM];                  // Whh transposed: [200][600]

// ---------------- generic NT GEMM with f32x2 packed math ----------------
// C = act(A@W^T + bias [+ base]); A:[M,K] lda, W:[N,K] ldw, C:[M,N] ldc.
#define TBM 128
#define TBN 64
#define TBK 16

enum { ACT_NONE = 0, ACT_RELU = 1, ACT_TANH = 2 };

template <int ACT, bool HAS_BASE>
__global__ void __launch_bounds__(256)
gemm_nt(const float* __restrict__ A, int lda,
        const float* __restrict__ W, int ldw,
        const float* __restrict__ bias,
        const float* __restrict__ base, int baseMask,
        float* __restrict__ C, int ldc,
        int M, int N, int K)
{
    __shared__ float As[TBK][TBM + 4];
    __shared__ float Ws[TBK][TBN + 4];

    const int bm  = blockIdx.y * TBM;
    const int bn  = blockIdx.x * TBN;
    const int tid = threadIdx.x;
    const int tcol = tid & 15;   // 16 cols of threads -> n
    const int trow = tid >> 4;   // 16 rows of threads -> m

    ull acc[4][4];   // [m-pair][n]
#pragma unroll
    for (int i = 0; i < 4; i++)
#pragma unroll
        for (int j = 0; j < 4; j++) acc[i][j] = 0ull;

    for (int k0 = 0; k0 < K; k0 += TBK) {
#pragma unroll
        for (int i = 0; i < 8; i++) {
            int e = tid + i * 256;
            int r = e >> 4, c = e & 15;
            int gm = bm + r, gk = k0 + c;
            float v = 0.f;
            if (gm < M && gk < K) v = A[(size_t)gm * lda + gk];
            As[c][r] = v;
        }
#pragma unroll
        for (int i = 0; i < 4; i++) {
            int e = tid + i * 256;
            int r = e >> 4, c = e & 15;
            int gn = bn + r, gk = k0 + c;
            float v = 0.f;
            if (gn < N && gk < K) v = W[(size_t)gn * ldw + gk];
            Ws[c][r] = v;
        }
        __syncthreads();

#pragma unroll
        for (int k = 0; k < TBK; k++) {
            const ull* arow = reinterpret_cast<const ull*>(&As[k][trow * 8]);
            ull a0 = arow[0], a1 = arow[1], a2 = arow[2], a3 = arow[3];
            float4 wv = *reinterpret_cast<const float4*>(&Ws[k][tcol * 4]);
            ull w0 = pack2(wv.x, wv.x);
            ull w1 = pack2(wv.y, wv.y);
            ull w2 = pack2(wv.z, wv.z);
            ull w3 = pack2(wv.w, wv.w);
            acc[0][0] = ffma2(a0, w0, acc[0][0]);
            acc[0][1] = ffma2(a0, w1, acc[0][1]);
            acc[0][2] = ffma2(a0, w2, acc[0][2]);
            acc[0][3] = ffma2(a0, w3, acc[0][3]);
            acc[1][0] = ffma2(a1, w0, acc[1][0]);
            acc[1][1] = ffma2(a1, w1, acc[1][1]);
            acc[1][2] = ffma2(a1, w2, acc[1][2]);
            acc[1][3] = ffma2(a1, w3, acc[1][3]);
            acc[2][0] = ffma2(a2, w0, acc[2][0]);
            acc[2][1] = ffma2(a2, w1, acc[2][1]);
            acc[2][2] = ffma2(a2, w2, acc[2][2]);
            acc[2][3] = ffma2(a2, w3, acc[2][3]);
            acc[3][0] = ffma2(a3, w0, acc[3][0]);
            acc[3][1] = ffma2(a3, w1, acc[3][1]);
            acc[3][2] = ffma2(a3, w2, acc[3][2]);
            acc[3][3] = ffma2(a3, w3, acc[3][3]);
        }
        __syncthreads();
    }

#pragma unroll
    for (int i = 0; i < 4; i++) {
        int gm0 = bm + trow * 8 + 2 * i;
        if (gm0 >= M) continue;
#pragma unroll
        for (int j = 0; j < 4; j++) {
            int gn = bn + tcol * 4 + j;
            if (gn >= N) continue;
            float2 v2 = unpack2(acc[i][j]);
            float bv = bias ? bias[gn] : 0.f;
#pragma unroll
            for (int s = 0; s < 2; s++) {
                int gm = gm0 + s;
                if (gm >= M) break;
                float v = (s == 0 ? v2.x : v2.y) + bv;
                if (HAS_BASE) v += base[(size_t)(gm & baseMask) * 600 + gn];
                if (ACT == ACT_RELU) v = fmaxf(v, 0.f);
                else if (ACT == ACT_TANH) v = tanhf(v);
                C[(size_t)gm * ldc + gn] = v;
            }
        }
    }
}

// ---------------- tiny-K first layer ----------------
__global__ void embed1_kernel(const float* __restrict__ X,
                              const float* __restrict__ W,
                              const float* __restrict__ B,
                              float* __restrict__ Y, int M, int K)
{
    int idx = blockIdx.x * blockDim.x + threadIdx.x;
    if (idx >= M * EMB) return;
    int m = idx / EMB, j = idx - m * EMB;
    const float* xr = X + (size_t)m * K;
    const float* wr = W + (size_t)j * K;
    float s = B[j];
    for (int k = 0; k < K; k++) s = fmaf(xr[k], wr[k], s);
    Y[idx] = fmaxf(s, 0.f);
}

// ---------------- Whh transpose: [600][200] -> [200][600] ----------------
__global__ void transpose_whh_kernel(const float* __restrict__ W,
                                     float* __restrict__ Wt)
{
    int idx = blockIdx.x * blockDim.x + threadIdx.x;
    if (idx >= GDIM * EMB) return;
    int c = idx / EMB, k = idx - c * EMB;
    Wt[k * GDIM + c] = W[idx];
}

// ---------------- persistent fused GRU scan ----------------
// 128 CTAs x 16 batch rows, all 100 steps in one launch.
// smem: h2s [200][9] ull (k-major, row-pairs, padded), ghs [600][18] float,
//       bhh_s [600] float. Total 60000 B (dynamic).
#define SCAN_CTAS    128
#define ROWS_PER     16
#define SCAN_THREADS 320
#define H2S_BYTES    (200 * 9 * 8)      // 14400
#define GHS_BYTES    (600 * 18 * 4)     // 43200
#define SCAN_SMEM    (H2S_BYTES + GHS_BYTES + 600 * 4)  // 60000

__global__ void __launch_bounds__(SCAN_THREADS, 1)
scan_kernel(const float* __restrict__ Wt,    // [200][600]
            const float* __restrict__ bhh,   // [600]
            const float* __restrict__ gi,    // [T][BSZ][600]
            float* __restrict__ hiddens)     // [T+1][BSZ][200]
{
    extern __shared__ char sm[];
    ull   (*h2s)[9]  = reinterpret_cast<ull(*)[9]>(sm);
    float (*ghs)[18] = reinterpret_cast<float(*)[18]>(sm + H2S_BYTES);
    float* bhh_s     = reinterpret_cast<float*>(sm + H2S_BYTES + GHS_BYTES);
    float* hsf       = reinterpret_cast<float*>(sm);   // float view of h2s, row stride 18

    const int tid = threadIdx.x;
    const int b0  = blockIdx.x * ROWS_PER;
    const float2* Wt2 = reinterpret_cast<const float2*>(Wt);

    // preload bhh
    for (int j = tid; j < GDIM; j += SCAN_THREADS) bhh_s[j] = bhh[j];

    // load h0 into smem (hsf[j*18 + r] = hiddens[(b0+r)*200 + j])
    for (int e = tid; e < ROWS_PER * EMB; e += SCAN_THREADS) {
        int r = e / EMB, j = e - r * EMB;
        hsf[j * 18 + r] = hiddens[(size_t)(b0 + r) * EMB + j];
    }
    __syncthreads();

    const bool active = (tid < 300);

    for (int t = 0; t < TST; t++) {
        // ---- gh = h @ Whh^T : each active thread owns cols (2t, 2t+1), 8 row-pairs ----
        if (active) {
            ull acc0[8], acc1[8];
#pragma unroll
            for (int p = 0; p < 8; p++) { acc0[p] = 0ull; acc1[p] = 0ull; }

            float2 wbuf[4];
#pragma unroll
            for (int i = 0; i < 4; i++) wbuf[i] = Wt2[i * 300 + tid];

#pragma unroll 4
            for (int k = 0; k < EMB; k++) {
                float2 w = wbuf[k & 3];
                if (k + 4 < EMB) wbuf[k & 3] = Wt2[(k + 4) * 300 + tid];
                ull w0 = pack2(w.x, w.x);
                ull w1 = pack2(w.y, w.y);
                ull h0 = h2s[k][0], h1 = h2s[k][1], h2 = h2s[k][2], h3 = h2s[k][3];
                ull h4 = h2s[k][4], h5 = h2s[k][5], h6 = h2s[k][6], h7 = h2s[k][7];
                acc0[0] = ffma2(h0, w0, acc0[0]);  acc1[0] = ffma2(h0, w1, acc1[0]);
                acc0[1] = ffma2(h1, w0, acc0[1]);  acc1[1] = ffma2(h1, w1, acc1[1]);
                acc0[2] = ffma2(h2, w0, acc0[2]);  acc1[2] = ffma2(h2, w1, acc1[2]);
                acc0[3] = ffma2(h3, w0, acc0[3]);  acc1[3] = ffma2(h3, w1, acc1[3]);
                acc0[4] = ffma2(h4, w0, acc0[4]);  acc1[4] = ffma2(h4, w1, acc1[4]);
                acc0[5] = ffma2(h5, w0, acc0[5]);  acc1[5] = ffma2(h5, w1, acc1[5]);
                acc0[6] = ffma2(h6, w0, acc0[6]);  acc1[6] = ffma2(h6, w1, acc1[6]);
                acc0[7] = ffma2(h7, w0, acc0[7]);  acc1[7] = ffma2(h7, w1, acc1[7]);
            }

            int c0 = 2 * tid, c1 = 2 * tid + 1;
            float2* g0 = reinterpret_cast<float2*>(&ghs[c0][0]);
            float2* g1 = reinterpret_cast<float2*>(&ghs[c1][0]);
#pragma unroll
            for (int p = 0; p < 8; p++) {
                float2 v0 = unpack2(acc0[p]);
                float2 v1 = unpack2(acc1[p]);
                g0[p] = v0;
                g1[p] = v1;
            }
        }
        __syncthreads();

        // ---- gate combine + in-place h update + global store ----
        {
            const float* gib = gi + ((size_t)t * BSZ + b0) * GDIM;
            float* hout = hiddens + ((size_t)(t + 1) * BSZ + b0) * EMB;
#pragma unroll
            for (int it = 0; it < (ROWS_PER * EMB) / SCAN_THREADS; it++) {
                int e = tid + it * SCAN_THREADS;
                int r = e / EMB, j = e - r * EMB;
                const float* gr = gib + (size_t)r * GDIM;
                float gir = gr[j];
                float giz = gr[j + 200];
                float gin = gr[j + 400];
                float ghr = ghs[j][r]       + bhh_s[j];
                float ghz = ghs[j + 200][r] + bhh_s[j + 200];
                float ghn = ghs[j + 400][r] + bhh_s[j + 400];
                float rg = 1.f / (1.f + expf(-(gir + ghr)));
                float z  = 1.f / (1.f + expf(-(giz + ghz)));
                float n  = tanhf(gin + rg * ghn);
                float hold = hsf[j * 18 + r];
                float hnew = (1.f - z) * n + z * hold;
                hsf[j * 18 + r] = hnew;
                hout[(size_t)r * EMB + j] = hnew;
            }
        }
        __syncthreads();
    }
}

// ---------------- 200 -> 12 projection, warp per row ----------------
template <int MODE> // 0: mean (linear), 1: std (sqrt(softplus(v)+eps))
__global__ void proj_kernel(const float* __restrict__ H,
                            const float* __restrict__ W2,
                            const float* __restrict__ b2,
                            float* __restrict__ out, int M)
{
    int warp = (blockIdx.x * blockDim.x + threadIdx.x) >> 5;
    int lane = threadIdx.x & 31;
    if (warp >= M) return;
    const float* row = H + (size_t)warp * EMB;
    float acc[SDIM];
#pragma unroll
    for (int s = 0; s < SDIM; s++) acc[s] = 0.f;
    for (int k = lane; k < EMB; k += 32) {
        float hv = row[k];
#pragma unroll
        for (int s = 0; s < SDIM; s++)
            acc[s] = fmaf(hv, W2[s * EMB + k], acc[s]);
    }
#pragma unroll
    for (int s = 0; s < SDIM; s++) {
#pragma unroll
        for (int off = 16; off > 0; off >>= 1)
            acc[s] += __shfl_xor_sync(0xffffffffu, acc[s], off);
    }
    if (lane == 0) {
        float* o = out + (size_t)warp * SDIM;
#pragma unroll
        for (int s = 0; s < SDIM; s++) {
            float v = acc[s] + b2[s];
            if (MODE == 1) {
                float sp = log1pf(expf(-fabsf(v))) + fmaxf(v, 0.f);
                v = sqrtf(sp + EPSV);
            }
            o[s] = v;
        }
    }
}

// ---------------- host-side helpers ----------------
static void launch_gemm(int act, const float* A, int lda, const float* W, int ldw,
                        const float* bias, const float* base, int baseMask,
                        float* C, int ldc, int M, int N, int K)
{
    dim3 grid((N + TBN - 1) / TBN, (M + TBM - 1) / TBM);
    dim3 blk(256);
    if (base) {
        if (act == ACT_NONE)      gemm_nt<ACT_NONE, true><<<grid, blk>>>(A, lda, W, ldw, bias, base, baseMask, C, ldc, M, N, K);
        else if (act == ACT_RELU) gemm_nt<ACT_RELU, true><<<grid, blk>>>(A, lda, W, ldw, bias, base, baseMask, C, ldc, M, N, K);
        else                      gemm_nt<ACT_TANH, true><<<grid, blk>>>(A, lda, W, ldw, bias, base, baseMask, C, ldc, M, N, K);
    } else {
        if (act == ACT_NONE)      gemm_nt<ACT_NONE, false><<<grid, blk>>>(A, lda, W, ldw, bias, nullptr, 0, C, ldc, M, N, K);
        else if (act == ACT_RELU) gemm_nt<ACT_RELU, false><<<grid, blk>>>(A, lda, W, ldw, bias, nullptr, 0, C, ldc, M, N, K);
        else                      gemm_nt<ACT_TANH, false><<<grid, blk>>>(A, lda, W, ldw, bias, nullptr, 0, C, ldc, M, N, K);
    }
}

extern "C" void kernel_launch(void* const* d_in, const int* in_sizes, int n_in,
                              void* d_out, int out_size)
{
    const float* x        = (const float*)d_in[0];
    const float* u        = (const float*)d_in[1];
    const float* ctx_mean = (const float*)d_in[2];
    const float* lctx     = (const float*)d_in[3];
    const float* se_w1 = (const float*)d_in[4];  const float* se_b1 = (const float*)d_in[5];
    const float* se_w2 = (const float*)d_in[6];  const float* se_b2 = (const float*)d_in[7];
    const float* ae_w1 = (const float*)d_in[8];  const float* ae_b1 = (const float*)d_in[9];
    const float* ae_w2 = (const float*)d_in[10]; const float* ae_b2 = (const float*)d_in[11];
    const float* ce_w1 = (const float*)d_in[12]; const float* ce_b1 = (const float*)d_in[13];
    const float* ce_w2 = (const float*)d_in[14]; const float* ce_b2 = (const float*)d_in[15];
    const float* lce_w1 = (const float*)d_in[16]; const float* lce_b1 = (const float*)d_in[17];
    const float* lce_w2 = (const float*)d_in[18]; const float* lce_b2 = (const float*)d_in[19];
    const float* dec_w1 = (const float*)d_in[20]; const float* dec_b1 = (const float*)d_in[21];
    const float* dec_w2 = (const float*)d_in[22]; const float* dec_b2 = (const float*)d_in[23];
    const float* gru_wih = (const float*)d_in[24]; const float* gru_bih = (const float*)d_in[25];
    const float* gru_whh = (const float*)d_in[26]; const float* gru_bhh = (const float*)d_in[27];
    const float* cov_w1 = (const float*)d_in[28]; const float* cov_b1 = (const float*)d_in[29];
    const float* cov_w2 = (const float*)d_in[30]; const float* cov_b2 = (const float*)d_in[31];

    float *p_h1s, *p_ctx, *p_gibase, *p_bigh1, *p_alc, *p_gi, *p_hid, *p_tmp, *p_wt;
    cudaGetSymbolAddress((void**)&p_h1s,    g_h1_small);
    cudaGetSymbolAddress((void**)&p_ctx,    g_ctx_embed);
    cudaGetSymbolAddress((void**)&p_gibase, g_gibase);
    cudaGetSymbolAddress((void**)&p_bigh1,  g_big_h1);
    cudaGetSymbolAddress((void**)&p_alc,    g_alc);
    cudaGetSymbolAddress((void**)&p_gi,     g_gi);
    cudaGetSymbolAddress((void**)&p_hid,    g_hiddens);
    cudaGetSymbolAddress((void**)&p_tmp,    g_tmp);
    cudaGetSymbolAddress((void**)&p_wt,     g_whh_t);

    cudaFuncSetAttribute(scan_kernel, cudaFuncAttributeMaxDynamicSharedMemorySize, SCAN_SMEM);

    float* out_mean = (float*)d_out;
    float* out_std  = out_mean + (size_t)MROWS * SDIM;

    const int eb = 256;

    // Whh transpose (tiny)
    transpose_whh_kernel<<<(GDIM * EMB + eb - 1) / eb, eb>>>(gru_whh, p_wt);

    // state_embed -> hiddens row block 0
    embed1_kernel<<<(BSZ * EMB + eb - 1) / eb, eb>>>(x, se_w1, se_b1, p_h1s, BSZ, SDIM);
    launch_gemm(ACT_TANH, p_h1s, EMB, se_w2, EMB, se_b2, nullptr, 0, p_hid, EMB, BSZ, EMB, EMB);

    // ctx_embed, then gi_base = ctx_embed @ Wih[:, :200]^T + b_ih
    embed1_kernel<<<(BSZ * EMB + eb - 1) / eb, eb>>>(ctx_mean, ce_w1, ce_b1, p_h1s, BSZ, 8);
    launch_gemm(ACT_RELU, p_h1s, EMB, ce_w2, EMB, ce_b2, nullptr, 0, p_ctx, EMB, BSZ, EMB, EMB);
    launch_gemm(ACT_NONE, p_ctx, EMB, gru_wih, GDIM, gru_bih, nullptr, 0, p_gibase, GDIM, BSZ, GDIM, EMB);

    // action embed (all T) -> g_alc cols [0,200)
    embed1_kernel<<<((size_t)MBIG * EMB + eb - 1) / eb, eb>>>(u, ae_w1, ae_b1, p_bigh1, MBIG, 4);
    launch_gemm(ACT_RELU, p_bigh1, EMB, ae_w2, EMB, ae_b2, nullptr, 0, p_alc, 400, MBIG, EMB, EMB);

    // local ctx embed (all T) -> g_alc cols [200,400)
    embed1_kernel<<<((size_t)MBIG * EMB + eb - 1) / eb, eb>>>(lctx, lce_w1, lce_b1, p_bigh1, MBIG, 6);
    launch_gemm(ACT_RELU, p_bigh1, EMB, lce_w2, EMB, lce_b2, nullptr, 0, p_alc + 200, 400, MBIG, EMB, EMB);

    // gi[t,b,:] = [a|lc] @ Wih[:, 200:600]^T + gi_base[b,:]
    launch_gemm(ACT_NONE, p_alc, 400, gru_wih + 200, GDIM, nullptr, p_gibase, BSZ - 1,
                p_gi, GDIM, MBIG, GDIM, 400);

    // fused persistent GRU scan (one launch, all 100 steps)
    scan_kernel<<<SCAN_CTAS, SCAN_THREADS, SCAN_SMEM>>>(p_wt, gru_bhh, p_gi, p_hid);

    // decode mean
    launch_gemm(ACT_RELU, p_hid, EMB, dec_w1, EMB, dec_b1, nullptr, 0, p_tmp, EMB, MROWS, EMB, EMB);
    {
        int blocks = (MROWS * 32 + 255) / 256;
        proj_kernel<0><<<blocks, 256>>>(p_tmp, dec_w2, dec_b2, out_mean, MROWS);
    }
    // cov -> std
    launch_gemm(ACT_RELU, p_hid, EMB, cov_w1, EMB, cov_b1, nullptr, 0, p_tmp, EMB, MROWS, EMB, EMB);
    {
        int blocks = (MROWS * 32 + 255) / 256;
        proj_kernel<1><<<blocks, 256>>>(p_tmp, cov_w2, cov_b2, out_std, MROWS);
    }

    (void)in_sizes; (void)n_in; (void)out_size;
}

// round 5
// speedup vs baseline: 2.2107x; 1.6849x over previous
#include <cuda_runtime.h>
#include <cstdint>

// ---------------- problem dims ----------------
#define BSZ   2048
#define TST   100
#define EMB   200
#define SDIM  12
#define GDIM  600            // 3*EMB
#define MBIG  (TST*BSZ)      // 204800 rows
#define MROWS ((TST+1)*BSZ)  // 206848 rows
#define EPSV  1e-4f

typedef unsigned long long ull;

__device__ __forceinline__ ull ffma2(ull a, ull b, ull c) {
    ull d;
    asm("fma.rn.f32x2 %0, %1, %2, %3;" : "=l"(d) : "l"(a), "l"(b), "l"(c));
    return d;
}
__device__ __forceinline__ ull pack2(float lo, float hi) {
    ull d;
    asm("mov.b64 %0, {%1, %2};" : "=l"(d) : "f"(lo), "f"(hi));
    return d;
}
__device__ __forceinline__ float2 unpack2(ull v) {
    float2 r;
    asm("mov.b64 {%0, %1}, %2;" : "=f"(r.x), "=f"(r.y) : "l"(v));
    return r;
}
__device__ __forceinline__ uint32_t to_tf32(float x) {
    uint32_t r;
    asm("cvt.rna.tf32.f32 %0, %1;" : "=r"(r) : "f"(x));
    return r;
}

// mma.sync m16n8k8 tf32: D = A@B + D (A row-major 16x8, B col-major 8x8)
__device__ __forceinline__ void mma_tf32(float c[4],
                                         uint32_t a0, uint32_t a1, uint32_t a2, uint32_t a3,
                                         uint32_t b0, uint32_t b1) {
    asm volatile(
        "mma.sync.aligned.m16n8k8.row.col.f32.tf32.tf32.f32 "
        "{%0,%1,%2,%3}, {%4,%5,%6,%7}, {%8,%9}, {%0,%1,%2,%3};"
        : "+f"(c[0]), "+f"(c[1]), "+f"(c[2]), "+f"(c[3])
        : "r"(a0), "r"(a1), "r"(a2), "r"(a3), "r"(b0), "r"(b1));
}

// ---------------- device scratch ----------------
__device__ __align__(128) float g_h1_small[BSZ * EMB];
__device__ __align__(128) float g_ctx_embed[BSZ * EMB];
__device__ __align__(128) float g_gibase[BSZ * GDIM];
__device__ __align__(128) float g_big_h1[(size_t)MBIG * EMB];
__device__ __align__(128) float g_alc[(size_t)MBIG * 400];
__device__ __align__(128) float g_gi[(size_t)MBIG * GDIM];
__device__ __align__(128) float g_hiddens[(size_t)MROWS * EMB];
__device__ __align__(128) float g_tmp[(size_t)MROWS * EMB];
__device__ __align__(128) float g_whh_t[EMB * GDIM];

// ---------------- tensor-core tf32 GEMM via mma.sync ----------------
// C = act(A@W^T + bias [+ base]); tile 128x128, K chunk 32.
// smem layout: row-major, pitch 36 floats (pad 4) -> conflict-free frag loads.
#define KPITCH 36

enum { ACT_NONE = 0, ACT_RELU = 1, ACT_TANH = 2 };

// stage [128 rows x 32 k] tile into smem (tf32-rounded), 256 threads
__device__ __forceinline__ void mm_stage(const float* __restrict__ src, int ld,
                                         int row0, int rowsValid,
                                         int k0, int K,
                                         uint32_t* __restrict__ sdst, int tid)
{
    const bool fullK = (k0 + 32 <= K);
#pragma unroll
    for (int pass = 0; pass < 4; pass++) {
        int e = tid + pass * 256;       // 0..1023
        int r = e >> 3;                 // row 0..127
        int c = e & 7;                  // float4 slot (k group)
        float4 v = make_float4(0.f, 0.f, 0.f, 0.f);
        if (r < rowsValid) {
            const float* p = src + (size_t)(row0 + r) * ld + k0 + c * 4;
            if (fullK) {
                v = *reinterpret_cast<const float4*>(p);
            } else {
                int kb = k0 + c * 4;
                if (kb + 0 < K) v.x = p[0];
                if (kb + 1 < K) v.y = p[1];
                if (kb + 2 < K) v.z = p[2];
                if (kb + 3 < K) v.w = p[3];
            }
        }
        uint32_t* d = sdst + r * KPITCH + c * 4;
        d[0] = to_tf32(v.x);
        d[1] = to_tf32(v.y);
        d[2] = to_tf32(v.z);
        d[3] = to_tf32(v.w);
    }
}

template <int ACT, bool HAS_BASE>
__global__ void __launch_bounds__(256, 2)
mm_gemm(const float* __restrict__ A, int lda,
        const float* __restrict__ W, int ldw,
        const float* __restrict__ bias,
        const float* __restrict__ base, int baseMask,
        float* __restrict__ C, int ldc,
        int M, int N, int K)
{
    __shared__ uint32_t As[128 * KPITCH];
    __shared__ uint32_t Bs[128 * KPITCH];

    const int tid  = threadIdx.x;
    const int wid  = tid >> 5;
    const int lane = tid & 31;
    const int warp_m = wid >> 1;       // 0..3 -> 32 rows each
    const int warp_n = wid & 1;        // 0..1 -> 64 cols each
    const int bm = blockIdx.y * 128;
    const int bn = blockIdx.x * 128;
    const int nValid = min(128, N - bn);

    const int lg = lane >> 2;          // group id 0..7
    const int lt = lane & 3;           // thread in group

    float acc[2][8][4];
#pragma unroll
    for (int mt = 0; mt < 2; mt++)
#pragma unroll
        for (int nt = 0; nt < 8; nt++)
#pragma unroll
            for (int j = 0; j < 4; j++) acc[mt][nt][j] = 0.f;

    const int nk = (K + 31) / 32;
    for (int kc = 0; kc < nk; kc++) {
        int k0 = kc * 32;
        mm_stage(A, lda, bm, 128,    k0, K, As, tid);
        mm_stage(W, ldw, bn, nValid, k0, K, Bs, tid);
        __syncthreads();

#pragma unroll
        for (int kk = 0; kk < 4; kk++) {
            const int kb = kk * 8;
            // A fragments for 2 m-tiles
            uint32_t af[2][4];
#pragma unroll
            for (int mt = 0; mt < 2; mt++) {
                int r = warp_m * 32 + mt * 16 + lg;
                const uint32_t* pa = As + r * KPITCH + kb + lt;
                af[mt][0] = pa[0];
                af[mt][1] = pa[8 * KPITCH];
                af[mt][2] = pa[4];
                af[mt][3] = pa[8 * KPITCH + 4];
            }
#pragma unroll
            for (int nt = 0; nt < 8; nt++) {
                int n = warp_n * 64 + nt * 8 + lg;
                const uint32_t* pb = Bs + n * KPITCH + kb + lt;
                uint32_t b0 = pb[0];
                uint32_t b1 = pb[4];
                mma_tf32(acc[0][nt], af[0][0], af[0][1], af[0][2], af[0][3], b0, b1);
                mma_tf32(acc[1][nt], af[1][0], af[1][1], af[1][2], af[1][3], b0, b1);
            }
        }
        __syncthreads();
    }

    // epilogue
#pragma unroll
    for (int mt = 0; mt < 2; mt++) {
        int gm0 = bm + warp_m * 32 + mt * 16 + lg;       // rows gm0, gm0+8
        float* crow0 = C + (size_t)gm0 * ldc;
        float* crow1 = C + (size_t)(gm0 + 8) * ldc;
        const float* base0 = HAS_BASE ? (base + (size_t)(gm0 & baseMask) * GDIM) : nullptr;
        const float* base1 = HAS_BASE ? (base + (size_t)((gm0 + 8) & baseMask) * GDIM) : nullptr;
#pragma unroll
        for (int nt = 0; nt < 8; nt++) {
            int gnl = warp_n * 64 + nt * 8 + lt * 2;     // local col (pair)
            if (gnl >= nValid) continue;
            int gn = bn + gnl;
            float b0v = bias ? bias[gn]     : 0.f;
            float b1v = bias ? bias[gn + 1] : 0.f;
            float v00 = acc[mt][nt][0] + b0v;
            float v01 = acc[mt][nt][1] + b1v;
            float v10 = acc[mt][nt][2] + b0v;
            float v11 = acc[mt][nt][3] + b1v;
            if (HAS_BASE) {
                v00 += base0[gn]; v01 += base0[gn + 1];
                v10 += base1[gn]; v11 += base1[gn + 1];
            }
            if (ACT == ACT_RELU) {
                v00 = fmaxf(v00, 0.f); v01 = fmaxf(v01, 0.f);
                v10 = fmaxf(v10, 0.f); v11 = fmaxf(v11, 0.f);
            } else if (ACT == ACT_TANH) {
                v00 = tanhf(v00); v01 = tanhf(v01);
                v10 = tanhf(v10); v11 = tanhf(v11);
            }
            *reinterpret_cast<float2*>(crow0 + gn) = make_float2(v00, v01);
            *reinterpret_cast<float2*>(crow1 + gn) = make_float2(v10, v11);
        }
    }
}

// ---------------- tiny-K first layer ----------------
__global__ void embed1_kernel(const float* __restrict__ X,
                              const float* __restrict__ W,
                              const float* __restrict__ B,
                              float* __restrict__ Y, int M, int K)
{
    int idx = blockIdx.x * blockDim.x + threadIdx.x;
    if (idx >= M * EMB) return;
    int m = idx / EMB, j = idx - m * EMB;
    const float* xr = X + (size_t)m * K;
    const float* wr = W + (size_t)j * K;
    float s = B[j];
    for (int k = 0; k < K; k++) s = fmaf(xr[k], wr[k], s);
    Y[idx] = fmaxf(s, 0.f);
}

// ---------------- Whh transpose: [600][200] -> [200][600] ----------------
__global__ void transpose_whh_kernel(const float* __restrict__ W,
                                     float* __restrict__ Wt)
{
    int idx = blockIdx.x * blockDim.x + threadIdx.x;
    if (idx >= GDIM * EMB) return;
    int c = idx / EMB, k = idx - c * EMB;
    Wt[k * GDIM + c] = W[idx];
}

// ---------------- persistent fused GRU scan ----------------
#define SCAN_CTAS    128
#define ROWS_PER     16
#define SCAN_THREADS 320
#define H2S_BYTES    (200 * 9 * 8)      // 14400
#define GHS_BYTES    (600 * 18 * 4)     // 43200
#define SCAN_SMEM    (H2S_BYTES + GHS_BYTES + 600 * 4)  // 60000

__global__ void __launch_bounds__(SCAN_THREADS, 1)
scan_kernel(const float* __restrict__ Wt,    // [200][600]
            const float* __restrict__ bhh,   // [600]
            const float* __restrict__ gi,    // [T][BSZ][600]
            float* __restrict__ hiddens)     // [T+1][BSZ][200]
{
    extern __shared__ char sm[];
    ull   (*h2s)[9]  = reinterpret_cast<ull(*)[9]>(sm);
    float (*ghs)[18] = reinterpret_cast<float(*)[18]>(sm + H2S_BYTES);
    float* bhh_s     = reinterpret_cast<float*>(sm + H2S_BYTES + GHS_BYTES);
    float* hsf       = reinterpret_cast<float*>(sm);

    const int tid = threadIdx.x;
    const int b0  = blockIdx.x * ROWS_PER;
    const float2* Wt2 = reinterpret_cast<const float2*>(Wt);

    for (int j = tid; j < GDIM; j += SCAN_THREADS) bhh_s[j] = bhh[j];
    for (int e = tid; e < ROWS_PER * EMB; e += SCAN_THREADS) {
        int r = e / EMB, j = e - r * EMB;
        hsf[j * 18 + r] = hiddens[(size_t)(b0 + r) * EMB + j];
    }
    __syncthreads();

    const bool active = (tid < 300);

    for (int t = 0; t < TST; t++) {
        if (active) {
            ull acc0[8], acc1[8];
#pragma unroll
            for (int p = 0; p < 8; p++) { acc0[p] = 0ull; acc1[p] = 0ull; }

            float2 wbuf[4];
#pragma unroll
            for (int i = 0; i < 4; i++) wbuf[i] = Wt2[i * 300 + tid];

#pragma unroll 4
            for (int k = 0; k < EMB; k++) {
                float2 w = wbuf[k & 3];
                if (k + 4 < EMB) wbuf[k & 3] = Wt2[(k + 4) * 300 + tid];
                ull w0 = pack2(w.x, w.x);
                ull w1 = pack2(w.y, w.y);
                ull h0 = h2s[k][0], h1 = h2s[k][1], h2 = h2s[k][2], h3 = h2s[k][3];
                ull h4 = h2s[k][4], h5 = h2s[k][5], h6 = h2s[k][6], h7 = h2s[k][7];
                acc0[0] = ffma2(h0, w0, acc0[0]);  acc1[0] = ffma2(h0, w1, acc1[0]);
                acc0[1] = ffma2(h1, w0, acc0[1]);  acc1[1] = ffma2(h1, w1, acc1[1]);
                acc0[2] = ffma2(h2, w0, acc0[2]);  acc1[2] = ffma2(h2, w1, acc1[2]);
                acc0[3] = ffma2(h3, w0, acc0[3]);  acc1[3] = ffma2(h3, w1, acc1[3]);
                acc0[4] = ffma2(h4, w0, acc0[4]);  acc1[4] = ffma2(h4, w1, acc1[4]);
                acc0[5] = ffma2(h5, w0, acc0[5]);  acc1[5] = ffma2(h5, w1, acc1[5]);
                acc0[6] = ffma2(h6, w0, acc0[6]);  acc1[6] = ffma2(h6, w1, acc1[6]);
                acc0[7] = ffma2(h7, w0, acc0[7]);  acc1[7] = ffma2(h7, w1, acc1[7]);
            }

            int c0 = 2 * tid, c1 = 2 * tid + 1;
            float2* g0 = reinterpret_cast<float2*>(&ghs[c0][0]);
            float2* g1 = reinterpret_cast<float2*>(&ghs[c1][0]);
#pragma unroll
            for (int p = 0; p < 8; p++) {
                g0[p] = unpack2(acc0[p]);
                g1[p] = unpack2(acc1[p]);
            }
        }
        __syncthreads();

        {
            const float* gib = gi + ((size_t)t * BSZ + b0) * GDIM;
            float* hout = hiddens + ((size_t)(t + 1) * BSZ + b0) * EMB;
#pragma unroll
            for (int it = 0; it < (ROWS_PER * EMB) / SCAN_THREADS; it++) {
                int e = tid + it * SCAN_THREADS;
                int r = e / EMB, j = e - r * EMB;
                const float* gr = gib + (size_t)r * GDIM;
                float gir = gr[j];
                float giz = gr[j + 200];
                float gin = gr[j + 400];
                float ghr = ghs[j][r]       + bhh_s[j];
                float ghz = ghs[j + 200][r] + bhh_s[j + 200];
                float ghn = ghs[j + 400][r] + bhh_s[j + 400];
                float rg = 1.f / (1.f + expf(-(gir + ghr)));
                float z  = 1.f / (1.f + expf(-(giz + ghz)));
                float n  = tanhf(gin + rg * ghn);
                float hold = hsf[j * 18 + r];
                float hnew = (1.f - z) * n + z * hold;
                hsf[j * 18 + r] = hnew;
                hout[(size_t)r * EMB + j] = hnew;
            }
        }
        __syncthreads();
    }
}

// ---------------- 200 -> 12 projection, warp per row ----------------
template <int MODE>
__global__ void proj_kernel(const float* __restrict__ H,
                            const float* __restrict__ W2,
                            const float* __restrict__ b2,
                            float* __restrict__ out, int M)
{
    int warp = (blockIdx.x * blockDim.x + threadIdx.x) >> 5;
    int lane = threadIdx.x & 31;
    if (warp >= M) return;
    const float* row = H + (size_t)warp * EMB;
    float acc[SDIM];
#pragma unroll
    for (int s = 0; s < SDIM; s++) acc[s] = 0.f;
    for (int k = lane; k < EMB; k += 32) {
        float hv = row[k];
#pragma unroll
        for (int s = 0; s < SDIM; s++)
            acc[s] = fmaf(hv, W2[s * EMB + k], acc[s]);
    }
#pragma unroll
    for (int s = 0; s < SDIM; s++) {
#pragma unroll
        for (int off = 16; off > 0; off >>= 1)
            acc[s] += __shfl_xor_sync(0xffffffffu, acc[s], off);
    }
    if (lane == 0) {
        float* o = out + (size_t)warp * SDIM;
#pragma unroll
        for (int s = 0; s < SDIM; s++) {
            float v = acc[s] + b2[s];
            if (MODE == 1) {
                float sp = log1pf(expf(-fabsf(v))) + fmaxf(v, 0.f);
                v = sqrtf(sp + EPSV);
            }
            o[s] = v;
        }
    }
}

// ---------------- host-side ----------------
static void launch_mm(int act, const float* A, int lda, const float* W, int ldw,
                      const float* bias, const float* base, int baseMask,
                      float* C, int ldc, int M, int N, int K)
{
    dim3 grid((N + 127) / 128, M / 128);
    dim3 blk(256);
    if (base) {
        if (act == ACT_NONE)      mm_gemm<ACT_NONE, true><<<grid, blk>>>(A, lda, W, ldw, bias, base, baseMask, C, ldc, M, N, K);
        else if (act == ACT_RELU) mm_gemm<ACT_RELU, true><<<grid, blk>>>(A, lda, W, ldw, bias, base, baseMask, C, ldc, M, N, K);
        else                      mm_gemm<ACT_TANH, true><<<grid, blk>>>(A, lda, W, ldw, bias, base, baseMask, C, ldc, M, N, K);
    } else {
        if (act == ACT_NONE)      mm_gemm<ACT_NONE, false><<<grid, blk>>>(A, lda, W, ldw, bias, nullptr, 0, C, ldc, M, N, K);
        else if (act == ACT_RELU) mm_gemm<ACT_RELU, false><<<grid, blk>>>(A, lda, W, ldw, bias, nullptr, 0, C, ldc, M, N, K);
        else                      mm_gemm<ACT_TANH, false><<<grid, blk>>>(A, lda, W, ldw, bias, nullptr, 0, C, ldc, M, N, K);
    }
}

extern "C" void kernel_launch(void* const* d_in, const int* in_sizes, int n_in,
                              void* d_out, int out_size)
{
    const float* x        = (const float*)d_in[0];
    const float* u        = (const float*)d_in[1];
    const float* ctx_mean = (const float*)d_in[2];
    const float* lctx     = (const float*)d_in[3];
    const float* se_w1 = (const float*)d_in[4];  const float* se_b1 = (const float*)d_in[5];
    const float* se_w2 = (const float*)d_in[6];  const float* se_b2 = (const float*)d_in[7];
    const float* ae_w1 = (const float*)d_in[8];  const float* ae_b1 = (const float*)d_in[9];
    const float* ae_w2 = (const float*)d_in[10]; const float* ae_b2 = (const float*)d_in[11];
    const float* ce_w1 = (const float*)d_in[12]; const float* ce_b1 = (const float*)d_in[13];
    const float* ce_w2 = (const float*)d_in[14]; const float* ce_b2 = (const float*)d_in[15];
    const float* lce_w1 = (const float*)d_in[16]; const float* lce_b1 = (const float*)d_in[17];
    const float* lce_w2 = (const float*)d_in[18]; const float* lce_b2 = (const float*)d_in[19];
    const float* dec_w1 = (const float*)d_in[20]; const float* dec_b1 = (const float*)d_in[21];
    const float* dec_w2 = (const float*)d_in[22]; const float* dec_b2 = (const float*)d_in[23];
    const float* gru_wih = (const float*)d_in[24]; const float* gru_bih = (const float*)d_in[25];
    const float* gru_whh = (const float*)d_in[26]; const float* gru_bhh = (const float*)d_in[27];
    const float* cov_w1 = (const float*)d_in[28]; const float* cov_b1 = (const float*)d_in[29];
    const float* cov_w2 = (const float*)d_in[30]; const float* cov_b2 = (const float*)d_in[31];

    float *p_h1s, *p_ctx, *p_gibase, *p_bigh1, *p_alc, *p_gi, *p_hid, *p_tmp, *p_wt;
    cudaGetSymbolAddress((void**)&p_h1s,    g_h1_small);
    cudaGetSymbolAddress((void**)&p_ctx,    g_ctx_embed);
    cudaGetSymbolAddress((void**)&p_gibase, g_gibase);
    cudaGetSymbolAddress((void**)&p_bigh1,  g_big_h1);
    cudaGetSymbolAddress((void**)&p_alc,    g_alc);
    cudaGetSymbolAddress((void**)&p_gi,     g_gi);
    cudaGetSymbolAddress((void**)&p_hid,    g_hiddens);
    cudaGetSymbolAddress((void**)&p_tmp,    g_tmp);
    cudaGetSymbolAddress((void**)&p_wt,     g_whh_t);

    cudaFuncSetAttribute(scan_kernel, cudaFuncAttributeMaxDynamicSharedMemorySize, SCAN_SMEM);

    float* out_mean = (float*)d_out;
    float* out_std  = out_mean + (size_t)MROWS * SDIM;

    const int eb = 256;

    transpose_whh_kernel<<<(GDIM * EMB + eb - 1) / eb, eb>>>(gru_whh, p_wt);

    // state_embed -> hiddens block 0
    embed1_kernel<<<(BSZ * EMB + eb - 1) / eb, eb>>>(x, se_w1, se_b1, p_h1s, BSZ, SDIM);
    launch_mm(ACT_TANH, p_h1s, EMB, se_w2, EMB, se_b2, nullptr, 0, p_hid, EMB, BSZ, EMB, EMB);

    // ctx_embed, then gi_base
    embed1_kernel<<<(BSZ * EMB + eb - 1) / eb, eb>>>(ctx_mean, ce_w1, ce_b1, p_h1s, BSZ, 8);
    launch_mm(ACT_RELU, p_h1s, EMB, ce_w2, EMB, ce_b2, nullptr, 0, p_ctx, EMB, BSZ, EMB, EMB);
    launch_mm(ACT_NONE, p_ctx, EMB, gru_wih, GDIM, gru_bih, nullptr, 0, p_gibase, GDIM, BSZ, GDIM, EMB);

    // action embed (all T) -> alc[:, 0:200]
    embed1_kernel<<<((size_t)MBIG * EMB + eb - 1) / eb, eb>>>(u, ae_w1, ae_b1, p_bigh1, MBIG, 4);
    launch_mm(ACT_RELU, p_bigh1, EMB, ae_w2, EMB, ae_b2, nullptr, 0, p_alc, 400, MBIG, EMB, EMB);

    // local ctx embed -> alc[:, 200:400]
    embed1_kernel<<<((size_t)MBIG * EMB + eb - 1) / eb, eb>>>(lctx, lce_w1, lce_b1, p_bigh1, MBIG, 6);
    launch_mm(ACT_RELU, p_bigh1, EMB, lce_w2, EMB, lce_b2, nullptr, 0, p_alc + 200, 400, MBIG, EMB, EMB);

    // gi = [a|lc] @ Wih[:,200:600]^T + gi_base
    launch_mm(ACT_NONE, p_alc, 400, gru_wih + 200, GDIM, nullptr, p_gibase, BSZ - 1,
              p_gi, GDIM, MBIG, GDIM, 400);

    // fused persistent GRU scan
    scan_kernel<<<SCAN_CTAS, SCAN_THREADS, SCAN_SMEM>>>(p_wt, gru_bhh, p_gi, p_hid);

    // decode mean
    launch_mm(ACT_RELU, p_hid, EMB, dec_w1, EMB, dec_b1, nullptr, 0, p_tmp, EMB, MROWS, EMB, EMB);
    {
        int blocks = (MROWS * 32 + 255) / 256;
        proj_kernel<0><<<blocks, 256>>>(p_tmp, dec_w2, dec_b2, out_mean, MROWS);
    }
    // cov -> std
    launch_mm(ACT_RELU, p_hid, EMB, cov_w1, EMB, cov_b1, nullptr, 0, p_tmp, EMB, MROWS, EMB, EMB);
    {
        int blocks = (MROWS * 32 + 255) / 256;
        proj_kernel<1><<<blocks, 256>>>(p_tmp, cov_w2, cov_b2, out_std, MROWS);
    }

    (void)in_sizes; (void)n_in; (void)out_size;
}

// round 6
// speedup vs baseline: 2.3297x; 1.0538x over previous
#include <cuda_runtime.h>
#include <cstdint>

// ---------------- problem dims ----------------
#define BSZ   2048
#define TST   100
#define EMB   200
#define SDIM  12
#define GDIM  600            // 3*EMB
#define MBIG  (TST*BSZ)      // 204800 rows
#define MROWS ((TST+1)*BSZ)  // 206848 rows
#define EPSV  1e-4f

typedef unsigned long long ull;

__device__ __forceinline__ ull ffma2(ull a, ull b, ull c) {
    ull d;
    asm("fma.rn.f32x2 %0, %1, %2, %3;" : "=l"(d) : "l"(a), "l"(b), "l"(c));
    return d;
}
__device__ __forceinline__ ull pack2(float lo, float hi) {
    ull d;
    asm("mov.b64 %0, {%1, %2};" : "=l"(d) : "f"(lo), "f"(hi));
    return d;
}
__device__ __forceinline__ float2 unpack2(ull v) {
    float2 r;
    asm("mov.b64 {%0, %1}, %2;" : "=f"(r.x), "=f"(r.y) : "l"(v));
    return r;
}
__device__ __forceinline__ uint32_t to_tf32(float x) {
    uint32_t r;
    asm("cvt.rna.tf32.f32 %0, %1;" : "=r"(r) : "f"(x));
    return r;
}
__device__ __forceinline__ float round_tf32f(float x) {
    return __uint_as_float(to_tf32(x));
}
__device__ __forceinline__ uint32_t smem_u32(const void* p) {
    uint32_t a;
    asm("{ .reg .u64 t; cvta.to.shared.u64 t, %1; cvt.u32.u64 %0, t; }" : "=r"(a) : "l"(p));
    return a;
}

// mma.sync m16n8k8 tf32: D = A@B + D
__device__ __forceinline__ void mma_tf32(float c[4],
                                         uint32_t a0, uint32_t a1, uint32_t a2, uint32_t a3,
                                         uint32_t b0, uint32_t b1) {
    asm volatile(
        "mma.sync.aligned.m16n8k8.row.col.f32.tf32.tf32.f32 "
        "{%0,%1,%2,%3}, {%4,%5,%6,%7}, {%8,%9}, {%0,%1,%2,%3};"
        : "+f"(c[0]), "+f"(c[1]), "+f"(c[2]), "+f"(c[3])
        : "r"(a0), "r"(a1), "r"(a2), "r"(a3), "r"(b0), "r"(b1));
}

__device__ __forceinline__ void cp16(uint32_t daddr, const float* src, uint32_t bytes) {
    asm volatile("cp.async.ca.shared.global [%0], [%1], 16, %2;"
                 :: "r"(daddr), "l"(src), "r"(bytes));
}
#define CP_COMMIT()  asm volatile("cp.async.commit_group;" ::: "memory")
#define CP_WAIT_1()  asm volatile("cp.async.wait_group 1;" ::: "memory")
#define CP_WAIT_0()  asm volatile("cp.async.wait_group 0;" ::: "memory")

// ---------------- device scratch ----------------
__device__ __align__(128) float g_h1_small[BSZ * EMB];
__device__ __align__(128) float g_ctx_embed[BSZ * EMB];
__device__ __align__(128) float g_gibase[BSZ * GDIM];
__device__ __align__(128) float g_big_h1[(size_t)MBIG * EMB];
__device__ __align__(128) float g_alc[(size_t)MBIG * 400];
__device__ __align__(128) float g_gi[(size_t)MBIG * GDIM];
__device__ __align__(128) float g_hiddens[(size_t)MROWS * EMB];
__device__ __align__(128) float g_tmp[(size_t)MROWS * EMB];
__device__ __align__(128) float g_whh_t[EMB * GDIM];
__device__ __align__(128) float g_wrnd[600000];          // tf32-rounded weights

// rounded-weight offsets
#define WR_SE   0
#define WR_CE   40000
#define WR_AE   80000
#define WR_LCE  120000
#define WR_DEC  160000
#define WR_COV  200000
#define WR_WIH  240000   // 600x600

// ---------------- tensor-core tf32 GEMM (cp.async double-buffered) ----------------
#define KPITCH    36
#define CHUNK_U32 (128 * KPITCH)
#define MM_SMEM_BYTES (2 * 2 * CHUNK_U32 * 4)   // 73728

enum { ACT_NONE = 0, ACT_RELU = 1, ACT_TANH = 2 };

// issue cp.async for one [128 x 32] tile (raw fp32 bits; zero-fill tails)
__device__ __forceinline__ void mm_stage_cp(uint32_t sbase, const float* __restrict__ src,
                                            int ld, int row0, int rowsValid,
                                            int k0, int K, int tid)
{
#pragma unroll
    for (int pass = 0; pass < 4; pass++) {
        int e = tid + pass * 256;
        int r = e >> 3, c = e & 7;
        int ks = k0 + c * 4;
        int valid = (r < rowsValid) ? (min(max(K - ks, 0), 4) * 4) : 0;
        int rr = (r < rowsValid) ? r : 0;
        int kk = valid ? ks : 0;
        const float* g = src + (size_t)(row0 + rr) * ld + kk;
        cp16(sbase + (uint32_t)(r * KPITCH + c * 4) * 4u, g, (uint32_t)valid);
    }
}

template <int ACT, bool HAS_BASE>
__global__ void __launch_bounds__(256, 2)
mm_gemm(const float* __restrict__ A, int lda,
        const float* __restrict__ W, int ldw,
        const float* __restrict__ bias,
        const float* __restrict__ base, int baseMask,
        float* __restrict__ C, int ldc,
        int M, int N, int K, int cvtOut)
{
    extern __shared__ uint32_t sm_u32[];
    const uint32_t smem_base = smem_u32(sm_u32);

    const int tid  = threadIdx.x;
    const int wid  = tid >> 5;
    const int lane = tid & 31;
    const int warp_m = wid >> 1;       // 0..3 -> 32 rows each
    const int warp_n = wid & 1;        // 0..1 -> 64 cols each
    const int bm = blockIdx.y * 128;
    const int bn = blockIdx.x * 128;
    const int nValid = min(128, N - bn);

    const int lg = lane >> 2;          // group id 0..7
    const int lt = lane & 3;           // thread in group

    float acc[2][8][4];
#pragma unroll
    for (int mt = 0; mt < 2; mt++)
#pragma unroll
        for (int nt = 0; nt < 8; nt++)
#pragma unroll
            for (int j = 0; j < 4; j++) acc[mt][nt][j] = 0.f;

    const int nk = (K + 31) / 32;

    // prologue: stage chunk 0 into buffer 0
    mm_stage_cp(smem_base,                       A, lda, bm, 128,    0, K, tid);
    mm_stage_cp(smem_base + CHUNK_U32 * 4,       W, ldw, bn, nValid, 0, K, tid);
    CP_COMMIT();

    for (int kc = 0; kc < nk; kc++) {
        if (kc + 1 < nk) {
            uint32_t nb = smem_base + (uint32_t)(((kc + 1) & 1) * 2 * CHUNK_U32) * 4u;
            int k0n = (kc + 1) * 32;
            mm_stage_cp(nb,                 A, lda, bm, 128,    k0n, K, tid);
            mm_stage_cp(nb + CHUNK_U32 * 4, W, ldw, bn, nValid, k0n, K, tid);
            CP_COMMIT();
            CP_WAIT_1();
        } else {
            CP_WAIT_0();
        }
        __syncthreads();

        const uint32_t* As = sm_u32 + (kc & 1) * 2 * CHUNK_U32;
        const uint32_t* Bs = As + CHUNK_U32;

#pragma unroll
        for (int kk = 0; kk < 4; kk++) {
            const int kb = kk * 8;
            uint32_t af[2][4];
#pragma unroll
            for (int mt = 0; mt < 2; mt++) {
                int r = warp_m * 32 + mt * 16 + lg;
                const uint32_t* pa = As + r * KPITCH + kb + lt;
                af[mt][0] = pa[0];
                af[mt][1] = pa[8 * KPITCH];
                af[mt][2] = pa[4];
                af[mt][3] = pa[8 * KPITCH + 4];
            }
#pragma unroll
            for (int nt = 0; nt < 8; nt++) {
                int n = warp_n * 64 + nt * 8 + lg;
                const uint32_t* pb = Bs + n * KPITCH + kb + lt;
                uint32_t b0 = pb[0];
                uint32_t b1 = pb[4];
                mma_tf32(acc[0][nt], af[0][0], af[0][1], af[0][2], af[0][3], b0, b1);
                mma_tf32(acc[1][nt], af[1][0], af[1][1], af[1][2], af[1][3], b0, b1);
            }
        }
        __syncthreads();
    }

    // epilogue
#pragma unroll
    for (int mt = 0; mt < 2; mt++) {
        int gm0 = bm + warp_m * 32 + mt * 16 + lg;       // rows gm0, gm0+8
        float* crow0 = C + (size_t)gm0 * ldc;
        float* crow1 = C + (size_t)(gm0 + 8) * ldc;
        const float* base0 = HAS_BASE ? (base + (size_t)(gm0 & baseMask) * GDIM) : nullptr;
        const float* base1 = HAS_BASE ? (base + (size_t)((gm0 + 8) & baseMask) * GDIM) : nullptr;
#pragma unroll
        for (int nt = 0; nt < 8; nt++) {
            int gnl = warp_n * 64 + nt * 8 + lt * 2;
            if (gnl >= nValid) continue;
            int gn = bn + gnl;
            float b0v = bias ? bias[gn]     : 0.f;
            float b1v = bias ? bias[gn + 1] : 0.f;
            float v00 = acc[mt][nt][0] + b0v;
            float v01 = acc[mt][nt][1] + b1v;
            float v10 = acc[mt][nt][2] + b0v;
            float v11 = acc[mt][nt][3] + b1v;
            if (HAS_BASE) {
                v00 += base0[gn]; v01 += base0[gn + 1];
                v10 += base1[gn]; v11 += base1[gn + 1];
            }
            if (ACT == ACT_RELU) {
                v00 = fmaxf(v00, 0.f); v01 = fmaxf(v01, 0.f);
                v10 = fmaxf(v10, 0.f); v11 = fmaxf(v11, 0.f);
            } else if (ACT == ACT_TANH) {
                v00 = tanhf(v00); v01 = tanhf(v01);
                v10 = tanhf(v10); v11 = tanhf(v11);
            }
            if (cvtOut) {
                v00 = round_tf32f(v00); v01 = round_tf32f(v01);
                v10 = round_tf32f(v10); v11 = round_tf32f(v11);
            }
            *reinterpret_cast<float2*>(crow0 + gn) = make_float2(v00, v01);
            *reinterpret_cast<float2*>(crow1 + gn) = make_float2(v10, v11);
        }
    }
}

// ---------------- tiny-K first layer (output tf32-rounded) ----------------
__global__ void embed1_kernel(const float* __restrict__ X,
                              const float* __restrict__ W,
                              const float* __restrict__ B,
                              float* __restrict__ Y, int M, int K)
{
    int idx = blockIdx.x * blockDim.x + threadIdx.x;
    if (idx >= M * EMB) return;
    int m = idx / EMB, j = idx - m * EMB;
    const float* xr = X + (size_t)m * K;
    const float* wr = W + (size_t)j * K;
    float s = B[j];
    for (int k = 0; k < K; k++) s = fmaf(xr[k], wr[k], s);
    Y[idx] = round_tf32f(fmaxf(s, 0.f));
}

// ---------------- round weights to tf32 ----------------
__global__ void round_tf32_kernel(const float* __restrict__ src,
                                  float* __restrict__ dst, int n)
{
    int i = blockIdx.x * blockDim.x + threadIdx.x;
    if (i < n) dst[i] = round_tf32f(src[i]);
}

// ---------------- Whh transpose ----------------
__global__ void transpose_whh_kernel(const float* __restrict__ W,
                                     float* __restrict__ Wt)
{
    int idx = blockIdx.x * blockDim.x + threadIdx.x;
    if (idx >= GDIM * EMB) return;
    int c = idx / EMB, k = idx - c * EMB;
    Wt[k * GDIM + c] = W[idx];
}

// ---------------- persistent fused GRU scan ----------------
#define SCAN_CTAS    128
#define ROWS_PER     16
#define SCAN_THREADS 320
#define H2S_BYTES    (200 * 9 * 8)
#define GHS_BYTES    (600 * 18 * 4)
#define SCAN_SMEM    (H2S_BYTES + GHS_BYTES + 600 * 4)

__global__ void __launch_bounds__(SCAN_THREADS, 1)
scan_kernel(const float* __restrict__ Wt,
            const float* __restrict__ bhh,
            const float* __restrict__ gi,
            float* __restrict__ hiddens)
{
    extern __shared__ char sm[];
    ull   (*h2s)[9]  = reinterpret_cast<ull(*)[9]>(sm);
    float (*ghs)[18] = reinterpret_cast<float(*)[18]>(sm + H2S_BYTES);
    float* bhh_s     = reinterpret_cast<float*>(sm + H2S_BYTES + GHS_BYTES);
    float* hsf       = reinterpret_cast<float*>(sm);

    const int tid = threadIdx.x;
    const int b0  = blockIdx.x * ROWS_PER;
    const float2* Wt2 = reinterpret_cast<const float2*>(Wt);

    for (int j = tid; j < GDIM; j += SCAN_THREADS) bhh_s[j] = bhh[j];
    for (int e = tid; e < ROWS_PER * EMB; e += SCAN_THREADS) {
        int r = e / EMB, j = e - r * EMB;
        hsf[j * 18 + r] = hiddens[(size_t)(b0 + r) * EMB + j];
    }
    __syncthreads();

    const bool active = (tid < 300);

    for (int t = 0; t < TST; t++) {
        if (active) {
            ull acc0[8], acc1[8];
#pragma unroll
            for (int p = 0; p < 8; p++) { acc0[p] = 0ull; acc1[p] = 0ull; }

            float2 wbuf[4];
#pragma unroll
            for (int i = 0; i < 4; i++) wbuf[i] = Wt2[i * 300 + tid];

#pragma unroll 4
            for (int k = 0; k < EMB; k++) {
                float2 w = wbuf[k & 3];
                if (k + 4 < EMB) wbuf[k & 3] = Wt2[(k + 4) * 300 + tid];
                ull w0 = pack2(w.x, w.x);
                ull w1 = pack2(w.y, w.y);
                ull h0 = h2s[k][0], h1 = h2s[k][1], h2 = h2s[k][2], h3 = h2s[k][3];
                ull h4 = h2s[k][4], h5 = h2s[k][5], h6 = h2s[k][6], h7 = h2s[k][7];
                acc0[0] = ffma2(h0, w0, acc0[0]);  acc1[0] = ffma2(h0, w1, acc1[0]);
                acc0[1] = ffma2(h1, w0, acc0[1]);  acc1[1] = ffma2(h1, w1, acc1[1]);
                acc0[2] = ffma2(h2, w0, acc0[2]);  acc1[2] = ffma2(h2, w1, acc1[2]);
                acc0[3] = ffma2(h3, w0, acc0[3]);  acc1[3] = ffma2(h3, w1, acc1[3]);
                acc0[4] = ffma2(h4, w0, acc0[4]);  acc1[4] = ffma2(h4, w1, acc1[4]);
                acc0[5] = ffma2(h5, w0, acc0[5]);  acc1[5] = ffma2(h5, w1, acc1[5]);
                acc0[6] = ffma2(h6, w0, acc0[6]);  acc1[6] = ffma2(h6, w1, acc1[6]);
                acc0[7] = ffma2(h7, w0, acc0[7]);  acc1[7] = ffma2(h7, w1, acc1[7]);
            }

            int c0 = 2 * tid, c1 = 2 * tid + 1;
            float2* g0 = reinterpret_cast<float2*>(&ghs[c0][0]);
            float2* g1 = reinterpret_cast<float2*>(&ghs[c1][0]);
#pragma unroll
            for (int p = 0; p < 8; p++) {
                g0[p] = unpack2(acc0[p]);
                g1[p] = unpack2(acc1[p]);
            }
        }
        __syncthreads();

        {
            const float* gib = gi + ((size_t)t * BSZ + b0) * GDIM;
            float* hout = hiddens + ((size_t)(t + 1) * BSZ + b0) * EMB;
#pragma unroll
            for (int it = 0; it < (ROWS_PER * EMB) / SCAN_THREADS; it++) {
                int e = tid + it * SCAN_THREADS;
                int r = e / EMB, j = e - r * EMB;
                const float* gr = gib + (size_t)r * GDIM;
                float gir = gr[j];
                float giz = gr[j + 200];
                float gin = gr[j + 400];
                float ghr = ghs[j][r]       + bhh_s[j];
                float ghz = ghs[j + 200][r] + bhh_s[j + 200];
                float ghn = ghs[j + 400][r] + bhh_s[j + 400];
                float rg = 1.f / (1.f + expf(-(gir + ghr)));
                float z  = 1.f / (1.f + expf(-(giz + ghz)));
                float n  = tanhf(gin + rg * ghn);
                float hold = hsf[j * 18 + r];
                float hnew = (1.f - z) * n + z * hold;
                hsf[j * 18 + r] = hnew;
                hout[(size_t)r * EMB + j] = round_tf32f(hnew);  // rounded copy for dec/cov GEMMs
            }
        }
        __syncthreads();
    }
}

// ---------------- 200 -> 12 projection ----------------
template <int MODE>
__global__ void proj_kernel(const float* __restrict__ H,
                            const float* __restrict__ W2,
                            const float* __restrict__ b2,
                            float* __restrict__ out, int M)
{
    int warp = (blockIdx.x * blockDim.x + threadIdx.x) >> 5;
    int lane = threadIdx.x & 31;
    if (warp >= M) return;
    const float* row = H + (size_t)warp * EMB;
    float acc[SDIM];
#pragma unroll
    for (int s = 0; s < SDIM; s++) acc[s] = 0.f;
    for (int k = lane; k < EMB; k += 32) {
        float hv = row[k];
#pragma unroll
        for (int s = 0; s < SDIM; s++)
            acc[s] = fmaf(hv, W2[s * EMB + k], acc[s]);
    }
#pragma unroll
    for (int s = 0; s < SDIM; s++) {
#pragma unroll
        for (int off = 16; off > 0; off >>= 1)
            acc[s] += __shfl_xor_sync(0xffffffffu, acc[s], off);
    }
    if (lane == 0) {
        float* o = out + (size_t)warp * SDIM;
#pragma unroll
        for (int s = 0; s < SDIM; s++) {
            float v = acc[s] + b2[s];
            if (MODE == 1) {
                float sp = log1pf(expf(-fabsf(v))) + fmaxf(v, 0.f);
                v = sqrtf(sp + EPSV);
            }
            o[s] = v;
        }
    }
}

// ---------------- host-side ----------------
static void launch_mm(int act, const float* A, int lda, const float* W, int ldw,
                      const float* bias, const float* base, int baseMask,
                      float* C, int ldc, int M, int N, int K, int cvtOut)
{
    dim3 grid((N + 127) / 128, M / 128);
    dim3 blk(256);
    size_t shm = MM_SMEM_BYTES;
    if (base) {
        if (act == ACT_NONE)      mm_gemm<ACT_NONE, true><<<grid, blk, shm>>>(A, lda, W, ldw, bias, base, baseMask, C, ldc, M, N, K, cvtOut);
        else if (act == ACT_RELU) mm_gemm<ACT_RELU, true><<<grid, blk, shm>>>(A, lda, W, ldw, bias, base, baseMask, C, ldc, M, N, K, cvtOut);
        else                      mm_gemm<ACT_TANH, true><<<grid, blk, shm>>>(A, lda, W, ldw, bias, base, baseMask, C, ldc, M, N, K, cvtOut);
    } else {
        if (act == ACT_NONE)      mm_gemm<ACT_NONE, false><<<grid, blk, shm>>>(A, lda, W, ldw, bias, nullptr, 0, C, ldc, M, N, K, cvtOut);
        else if (act == ACT_RELU) mm_gemm<ACT_RELU, false><<<grid, blk, shm>>>(A, lda, W, ldw, bias, nullptr, 0, C, ldc, M, N, K, cvtOut);
        else                      mm_gemm<ACT_TANH, false><<<grid, blk, shm>>>(A, lda, W, ldw, bias, nullptr, 0, C, ldc, M, N, K, cvtOut);
    }
}

extern "C" void kernel_launch(void* const* d_in, const int* in_sizes, int n_in,
                              void* d_out, int out_size)
{
    const float* x        = (const float*)d_in[0];
    const float* u        = (const float*)d_in[1];
    const float* ctx_mean = (const float*)d_in[2];
    const float* lctx     = (const float*)d_in[3];
    const float* se_w1 = (const float*)d_in[4];  const float* se_b1 = (const float*)d_in[5];
    const float* se_w2 = (const float*)d_in[6];  const float* se_b2 = (const float*)d_in[7];
    const float* ae_w1 = (const float*)d_in[8];  const float* ae_b1 = (const float*)d_in[9];
    const float* ae_w2 = (const float*)d_in[10]; const float* ae_b2 = (const float*)d_in[11];
    const float* ce_w1 = (const float*)d_in[12]; const float* ce_b1 = (const float*)d_in[13];
    const float* ce_w2 = (const float*)d_in[14]; const float* ce_b2 = (const float*)d_in[15];
    const float* lce_w1 = (const float*)d_in[16]; const float* lce_b1 = (const float*)d_in[17];
    const float* lce_w2 = (const float*)d_in[18]; const float* lce_b2 = (const float*)d_in[19];
    const float* dec_w1 = (const float*)d_in[20]; const float* dec_b1 = (const float*)d_in[21];
    const float* dec_w2 = (const float*)d_in[22]; const float* dec_b2 = (const float*)d_in[23];
    const float* gru_wih = (const float*)d_in[24]; const float* gru_bih = (const float*)d_in[25];
    const float* gru_whh = (const float*)d_in[26]; const float* gru_bhh = (const float*)d_in[27];
    const float* cov_w1 = (const float*)d_in[28]; const float* cov_b1 = (const float*)d_in[29];
    const float* cov_w2 = (const float*)d_in[30]; const float* cov_b2 = (const float*)d_in[31];

    float *p_h1s, *p_ctx, *p_gibase, *p_bigh1, *p_alc, *p_gi, *p_hid, *p_tmp, *p_wt, *p_wr;
    cudaGetSymbolAddress((void**)&p_h1s,    g_h1_small);
    cudaGetSymbolAddress((void**)&p_ctx,    g_ctx_embed);
    cudaGetSymbolAddress((void**)&p_gibase, g_gibase);
    cudaGetSymbolAddress((void**)&p_bigh1,  g_big_h1);
    cudaGetSymbolAddress((void**)&p_alc,    g_alc);
    cudaGetSymbolAddress((void**)&p_gi,     g_gi);
    cudaGetSymbolAddress((void**)&p_hid,    g_hiddens);
    cudaGetSymbolAddress((void**)&p_tmp,    g_tmp);
    cudaGetSymbolAddress((void**)&p_wt,     g_whh_t);
    cudaGetSymbolAddress((void**)&p_wr,     g_wrnd);

    cudaFuncSetAttribute(scan_kernel, cudaFuncAttributeMaxDynamicSharedMemorySize, SCAN_SMEM);
    cudaFuncSetAttribute(mm_gemm<ACT_NONE, true>,  cudaFuncAttributeMaxDynamicSharedMemorySize, MM_SMEM_BYTES);
    cudaFuncSetAttribute(mm_gemm<ACT_RELU, true>,  cudaFuncAttributeMaxDynamicSharedMemorySize, MM_SMEM_BYTES);
    cudaFuncSetAttribute(mm_gemm<ACT_TANH, true>,  cudaFuncAttributeMaxDynamicSharedMemorySize, MM_SMEM_BYTES);
    cudaFuncSetAttribute(mm_gemm<ACT_NONE, false>, cudaFuncAttributeMaxDynamicSharedMemorySize, MM_SMEM_BYTES);
    cudaFuncSetAttribute(mm_gemm<ACT_RELU, false>, cudaFuncAttributeMaxDynamicSharedMemorySize, MM_SMEM_BYTES);
    cudaFuncSetAttribute(mm_gemm<ACT_TANH, false>, cudaFuncAttributeMaxDynamicSharedMemorySize, MM_SMEM_BYTES);

    float* out_mean = (float*)d_out;
    float* out_std  = out_mean + (size_t)MROWS * SDIM;

    const int eb = 256;

    // round all MMA weight operands once
    round_tf32_kernel<<<(40000 + eb - 1) / eb, eb>>>(se_w2,  p_wr + WR_SE,  40000);
    round_tf32_kernel<<<(40000 + eb - 1) / eb, eb>>>(ce_w2,  p_wr + WR_CE,  40000);
    round_tf32_kernel<<<(40000 + eb - 1) / eb, eb>>>(ae_w2,  p_wr + WR_AE,  40000);
    round_tf32_kernel<<<(40000 + eb - 1) / eb, eb>>>(lce_w2, p_wr + WR_LCE, 40000);
    round_tf32_kernel<<<(40000 + eb - 1) / eb, eb>>>(dec_w1, p_wr + WR_DEC, 40000);
    round_tf32_kernel<<<(40000 + eb - 1) / eb, eb>>>(cov_w1, p_wr + WR_COV, 40000);
    round_tf32_kernel<<<(360000 + eb - 1) / eb, eb>>>(gru_wih, p_wr + WR_WIH, 360000);

    transpose_whh_kernel<<<(GDIM * EMB + eb - 1) / eb, eb>>>(gru_whh, p_wt);

    // state_embed -> hiddens block 0 (rounded output feeds dec/cov GEMMs + scan h0)
    embed1_kernel<<<(BSZ * EMB + eb - 1) / eb, eb>>>(x, se_w1, se_b1, p_h1s, BSZ, SDIM);
    launch_mm(ACT_TANH, p_h1s, EMB, p_wr + WR_SE, EMB, se_b2, nullptr, 0, p_hid, EMB, BSZ, EMB, EMB, 1);

    // ctx_embed, then gi_base
    embed1_kernel<<<(BSZ * EMB + eb - 1) / eb, eb>>>(ctx_mean, ce_w1, ce_b1, p_h1s, BSZ, 8);
    launch_mm(ACT_RELU, p_h1s, EMB, p_wr + WR_CE, EMB, ce_b2, nullptr, 0, p_ctx, EMB, BSZ, EMB, EMB, 1);
    launch_mm(ACT_NONE, p_ctx, EMB, p_wr + WR_WIH, GDIM, gru_bih, nullptr, 0, p_gibase, GDIM, BSZ, GDIM, EMB, 0);

    // action embed (all T) -> alc[:, 0:200]
    embed1_kernel<<<((size_t)MBIG * EMB + eb - 1) / eb, eb>>>(u, ae_w1, ae_b1, p_bigh1, MBIG, 4);
    launch_mm(ACT_RELU, p_bigh1, EMB, p_wr + WR_AE, EMB, ae_b2, nullptr, 0, p_alc, 400, MBIG, EMB, EMB, 1);

    // local ctx embed -> alc[:, 200:400]
    embed1_kernel<<<((size_t)MBIG * EMB + eb - 1) / eb, eb>>>(lctx, lce_w1, lce_b1, p_bigh1, MBIG, 6);
    launch_mm(ACT_RELU, p_bigh1, EMB, p_wr + WR_LCE, EMB, lce_b2, nullptr, 0, p_alc + 200, 400, MBIG, EMB, EMB, 1);

    // gi = [a|lc] @ Wih[:,200:600]^T + gi_base
    launch_mm(ACT_NONE, p_alc, 400, p_wr + WR_WIH + 200, GDIM, nullptr, p_gibase, BSZ - 1,
              p_gi, GDIM, MBIG, GDIM, 400, 0);

    // fused persistent GRU scan
    scan_kernel<<<SCAN_CTAS, SCAN_THREADS, SCAN_SMEM>>>(p_wt, gru_bhh, p_gi, p_hid);

    // decode mean
    launch_mm(ACT_RELU, p_hid, EMB, p_wr + WR_DEC, EMB, dec_b1, nullptr, 0, p_tmp, EMB, MROWS, EMB, EMB, 0);
    {
        int blocks = (MROWS * 32 + 255) / 256;
        proj_kernel<0><<<blocks, 256>>>(p_tmp, dec_w2, dec_b2, out_mean, MROWS);
    }
    // cov -> std
    launch_mm(ACT_RELU, p_hid, EMB, p_wr + WR_COV, EMB, cov_b1, nullptr, 0, p_tmp, EMB, MROWS, EMB, EMB, 0);
    {
        int blocks = (MROWS * 32 + 255) / 256;
        proj_kernel<1><<<blocks, 256>>>(p_tmp, cov_w2, cov_b2, out_std, MROWS);
    }

    (void)in_sizes; (void)n_in; (void)out_size;
}

// round 7
// speedup vs baseline: 2.6975x; 1.1579x over previous
#include <cuda_runtime.h>
#include <cuda_fp16.h>
#include <cstdint>

// ---------------- problem dims ----------------
#define BSZ   2048
#define TST   100
#define EMB   200
#define SDIM  12
#define GDIM  600            // 3*EMB
#define MBIG  (TST*BSZ)      // 204800 rows
#define MROWS ((TST+1)*BSZ)  // 206848 rows
#define EPSV  1e-4f

typedef unsigned long long ull;

__device__ __forceinline__ ull ffma2(ull a, ull b, ull c) {
    ull d;
    asm("fma.rn.f32x2 %0, %1, %2, %3;" : "=l"(d) : "l"(a), "l"(b), "l"(c));
    return d;
}
__device__ __forceinline__ ull pack2(float lo, float hi) {
    ull d;
    asm("mov.b64 %0, {%1, %2};" : "=l"(d) : "f"(lo), "f"(hi));
    return d;
}
__device__ __forceinline__ float2 unpack2(ull v) {
    float2 r;
    asm("mov.b64 {%0, %1}, %2;" : "=f"(r.x), "=f"(r.y) : "l"(v));
    return r;
}
__device__ __forceinline__ uint32_t smem_u32(const void* p) {
    uint32_t a;
    asm("{ .reg .u64 t; cvta.to.shared.u64 t, %1; cvt.u32.u64 %0, t; }" : "=r"(a) : "l"(p));
    return a;
}

// mma.sync m16n8k16 f16 -> f32 accum
__device__ __forceinline__ void mma_f16(float c[4],
                                        uint32_t a0, uint32_t a1, uint32_t a2, uint32_t a3,
                                        uint32_t b0, uint32_t b1) {
    asm volatile(
        "mma.sync.aligned.m16n8k16.row.col.f32.f16.f16.f32 "
        "{%0,%1,%2,%3}, {%4,%5,%6,%7}, {%8,%9}, {%0,%1,%2,%3};"
        : "+f"(c[0]), "+f"(c[1]), "+f"(c[2]), "+f"(c[3])
        : "r"(a0), "r"(a1), "r"(a2), "r"(a3), "r"(b0), "r"(b1));
}

__device__ __forceinline__ void cp16h(uint32_t daddr, const __half* src, uint32_t bytes) {
    asm volatile("cp.async.ca.shared.global [%0], [%1], 16, %2;"
                 :: "r"(daddr), "l"(src), "r"(bytes));
}
#define CP_COMMIT()  asm volatile("cp.async.commit_group;" ::: "memory")
#define CP_WAIT_1()  asm volatile("cp.async.wait_group 1;" ::: "memory")
#define CP_WAIT_0()  asm volatile("cp.async.wait_group 0;" ::: "memory")

// ---------------- device scratch ----------------
__device__ __align__(128) float  g_gibase[BSZ * GDIM];
__device__ __align__(128) float  g_h0[BSZ * EMB];                 // fp32 h0 for scan
__device__ __align__(128) float  g_tmp[(size_t)MROWS * EMB];      // decode/cov hidden (fp32)
__device__ __align__(128) float  g_whh_t[EMB * GDIM];
__device__ __align__(128) __half g_h1h[(size_t)MBIG * EMB];       // embed layer-1 outputs (half)
__device__ __align__(128) __half g_ctxh[BSZ * EMB];
__device__ __align__(128) __half g_alch[(size_t)MBIG * 400];
__device__ __align__(128) __half g_gih[(size_t)MBIG * GDIM];      // precomputed input gates (half)
__device__ __align__(128) __half g_hidh[(size_t)MROWS * EMB];     // hiddens (half, GEMM input)
__device__ __align__(128) __half g_wh[600000];                    // half weights

// half-weight offsets
#define WH_SE   0
#define WH_CE   40000
#define WH_AE   80000
#define WH_LCE  120000
#define WH_DEC  160000
#define WH_COV  200000
#define WH_WIH  240000   // 600x600

// ---------------- fp16 tensor-core GEMM (cp.async double-buffered) ----------------
// C = act(A@W^T + bias [+ base]); A:[M,K] half, W:[N,K] half. Tile 128x128, K chunk 32.
#define HPITCH 40                 // halves per smem row
#define HP_W   20                 // 32-bit words per smem row
#define HTILE_U32 (128 * HP_W)    // 2560 words = 10240 B

enum { ACT_NONE = 0, ACT_RELU = 1, ACT_TANH = 2 };

__device__ __forceinline__ void stage_h(uint32_t sbase, const __half* __restrict__ src,
                                        int ld, int row0, int rowsValid,
                                        int k0, int K, int tid)
{
#pragma unroll
    for (int pass = 0; pass < 2; pass++) {
        int e = tid + pass * 256;      // 0..511
        int r = e >> 2, c = e & 3;     // row, 16B-slot (8 halves)
        int ks = k0 + c * 8;
        int valid = (r < rowsValid) ? min(max((K - ks) * 2, 0), 16) : 0;
        const __half* g = src + (size_t)(row0 + ((r < rowsValid) ? r : 0)) * ld + (valid ? ks : 0);
        cp16h(sbase + (uint32_t)(r * HPITCH + c * 8) * 2u, g, (uint32_t)valid);
    }
}

template <int ACT, bool HAS_BASE>
__global__ void __launch_bounds__(256, 2)
hm_gemm(const __half* __restrict__ A, int lda,
        const __half* __restrict__ W, int ldw,
        const float* __restrict__ bias,
        const float* __restrict__ base, int baseMask,
        float* __restrict__ outF, int ldf,
        __half* __restrict__ outH, int ldh,
        int M, int N, int K)
{
    __shared__ uint32_t smh[4 * HTILE_U32];   // [buf][A|B]
    const uint32_t smem_base = smem_u32(smh);

    const int tid  = threadIdx.x;
    const int wid  = tid >> 5;
    const int lane = tid & 31;
    const int warp_m = wid >> 1;       // 0..3 -> 32 rows each
    const int warp_n = wid & 1;        // 0..1 -> 64 cols each
    const int bm = blockIdx.y * 128;
    const int bn = blockIdx.x * 128;
    const int nValid = min(128, N - bn);

    const int lg = lane >> 2;          // group id 0..7
    const int lt = lane & 3;           // thread in group

    float acc[2][8][4];
#pragma unroll
    for (int mt = 0; mt < 2; mt++)
#pragma unroll
        for (int nt = 0; nt < 8; nt++)
#pragma unroll
            for (int j = 0; j < 4; j++) acc[mt][nt][j] = 0.f;

    const int nk = (K + 31) / 32;

    // prologue: stage chunk 0 into buffer 0
    stage_h(smem_base,                   A, lda, bm, 128,    0, K, tid);
    stage_h(smem_base + HTILE_U32 * 4,   W, ldw, bn, nValid, 0, K, tid);
    CP_COMMIT();

    for (int kc = 0; kc < nk; kc++) {
        if (kc + 1 < nk) {
            uint32_t nb = smem_base + (uint32_t)(((kc + 1) & 1) * 2 * HTILE_U32) * 4u;
            int k0n = (kc + 1) * 32;
            stage_h(nb,                 A, lda, bm, 128,    k0n, K, tid);
            stage_h(nb + HTILE_U32 * 4, W, ldw, bn, nValid, k0n, K, tid);
            CP_COMMIT();
            CP_WAIT_1();
        } else {
            CP_WAIT_0();
        }
        __syncthreads();

        const uint32_t* As = smh + (kc & 1) * 2 * HTILE_U32;
        const uint32_t* Bs = As + HTILE_U32;

#pragma unroll
        for (int kk = 0; kk < 2; kk++) {
            const int kw = kk * 8;     // word offset (16 halves)
            uint32_t af[2][4];
#pragma unroll
            for (int mt = 0; mt < 2; mt++) {
                int r = warp_m * 32 + mt * 16 + lg;
                const uint32_t* pa = As + r * HP_W + kw + lt;
                af[mt][0] = pa[0];
                af[mt][1] = pa[8 * HP_W];
                af[mt][2] = pa[4];
                af[mt][3] = pa[8 * HP_W + 4];
            }
#pragma unroll
            for (int nt = 0; nt < 8; nt++) {
                int n = warp_n * 64 + nt * 8 + lg;
                const uint32_t* pb = Bs + n * HP_W + kw + lt;
                uint32_t b0 = pb[0];
                uint32_t b1 = pb[4];
                mma_f16(acc[0][nt], af[0][0], af[0][1], af[0][2], af[0][3], b0, b1);
                mma_f16(acc[1][nt], af[1][0], af[1][1], af[1][2], af[1][3], b0, b1);
            }
        }
        __syncthreads();
    }

    // epilogue
#pragma unroll
    for (int mt = 0; mt < 2; mt++) {
        int gm0 = bm + warp_m * 32 + mt * 16 + lg;       // rows gm0, gm0+8
        const float* base0 = HAS_BASE ? (base + (size_t)(gm0 & baseMask) * GDIM) : nullptr;
        const float* base1 = HAS_BASE ? (base + (size_t)((gm0 + 8) & baseMask) * GDIM) : nullptr;
#pragma unroll
        for (int nt = 0; nt < 8; nt++) {
            int gnl = warp_n * 64 + nt * 8 + lt * 2;
            if (gnl >= nValid) continue;
            int gn = bn + gnl;
            float b0v = bias ? bias[gn]     : 0.f;
            float b1v = bias ? bias[gn + 1] : 0.f;
            float v00 = acc[mt][nt][0] + b0v;
            float v01 = acc[mt][nt][1] + b1v;
            float v10 = acc[mt][nt][2] + b0v;
            float v11 = acc[mt][nt][3] + b1v;
            if (HAS_BASE) {
                v00 += base0[gn]; v01 += base0[gn + 1];
                v10 += base1[gn]; v11 += base1[gn + 1];
            }
            if (ACT == ACT_RELU) {
                v00 = fmaxf(v00, 0.f); v01 = fmaxf(v01, 0.f);
                v10 = fmaxf(v10, 0.f); v11 = fmaxf(v11, 0.f);
            } else if (ACT == ACT_TANH) {
                v00 = tanhf(v00); v01 = tanhf(v01);
                v10 = tanhf(v10); v11 = tanhf(v11);
            }
            if (outF) {
                *reinterpret_cast<float2*>(outF + (size_t)gm0 * ldf + gn)       = make_float2(v00, v01);
                *reinterpret_cast<float2*>(outF + (size_t)(gm0 + 8) * ldf + gn) = make_float2(v10, v11);
            }
            if (outH) {
                *reinterpret_cast<__half2*>(outH + (size_t)gm0 * ldh + gn)       = __floats2half2_rn(v00, v01);
                *reinterpret_cast<__half2*>(outH + (size_t)(gm0 + 8) * ldh + gn) = __floats2half2_rn(v10, v11);
            }
        }
    }
}

// ---------------- tiny-K first layer (half output) ----------------
__global__ void embed1_kernel(const float* __restrict__ X,
                              const float* __restrict__ W,
                              const float* __restrict__ B,
                              __half* __restrict__ Y, int M, int K)
{
    int idx = blockIdx.x * blockDim.x + threadIdx.x;
    if (idx >= M * EMB) return;
    int m = idx / EMB, j = idx - m * EMB;
    const float* xr = X + (size_t)m * K;
    const float* wr = W + (size_t)j * K;
    float s = B[j];
    for (int k = 0; k < K; k++) s = fmaf(xr[k], wr[k], s);
    Y[idx] = __float2half(fmaxf(s, 0.f));
}

// ---------------- convert all GEMM weights to half (one kernel) ----------------
__global__ void conv_w_kernel(const float* __restrict__ se, const float* __restrict__ ce,
                              const float* __restrict__ ae, const float* __restrict__ lce,
                              const float* __restrict__ dec, const float* __restrict__ cov,
                              const float* __restrict__ wih, __half* __restrict__ wh)
{
    int i = blockIdx.x * blockDim.x + threadIdx.x;
    if (i < 40000) {
        wh[WH_SE  + i] = __float2half(se[i]);
        wh[WH_CE  + i] = __float2half(ce[i]);
        wh[WH_AE  + i] = __float2half(ae[i]);
        wh[WH_LCE + i] = __float2half(lce[i]);
        wh[WH_DEC + i] = __float2half(dec[i]);
        wh[WH_COV + i] = __float2half(cov[i]);
    }
    if (i < 360000) wh[WH_WIH + i] = __float2half(wih[i]);
}

// ---------------- Whh transpose ----------------
__global__ void transpose_whh_kernel(const float* __restrict__ W,
                                     float* __restrict__ Wt)
{
    int idx = blockIdx.x * blockDim.x + threadIdx.x;
    if (idx >= GDIM * EMB) return;
    int c = idx / EMB, k = idx - c * EMB;
    Wt[k * GDIM + c] = W[idx];
}

// ---------------- persistent fused GRU scan ----------------
#define SCAN_CTAS    128
#define ROWS_PER     16
#define SCAN_THREADS 320
#define H2S_BYTES    (200 * 9 * 8)
#define GHS_BYTES    (600 * 18 * 4)
#define SCAN_SMEM    (H2S_BYTES + GHS_BYTES + 600 * 4)

__global__ void __launch_bounds__(SCAN_THREADS, 1)
scan_kernel(const float* __restrict__ Wt,     // [200][600]
            const float* __restrict__ bhh,    // [600]
            const __half* __restrict__ gih,   // [T][BSZ][600] half
            const float* __restrict__ h0,     // [BSZ][200] fp32
            __half* __restrict__ hidh)        // [T+1][BSZ][200] half out
{
    extern __shared__ char sm[];
    ull   (*h2s)[9]  = reinterpret_cast<ull(*)[9]>(sm);
    float (*ghs)[18] = reinterpret_cast<float(*)[18]>(sm + H2S_BYTES);
    float* bhh_s     = reinterpret_cast<float*>(sm + H2S_BYTES + GHS_BYTES);
    float* hsf       = reinterpret_cast<float*>(sm);

    const int tid = threadIdx.x;
    const int b0  = blockIdx.x * ROWS_PER;
    const float2* Wt2 = reinterpret_cast<const float2*>(Wt);

    for (int j = tid; j < GDIM; j += SCAN_THREADS) bhh_s[j] = bhh[j];
    for (int e = tid; e < ROWS_PER * EMB; e += SCAN_THREADS) {
        int r = e / EMB, j = e - r * EMB;
        hsf[j * 18 + r] = h0[(size_t)(b0 + r) * EMB + j];
    }
    __syncthreads();

    const bool active = (tid < 300);

    for (int t = 0; t < TST; t++) {
        if (active) {
            ull acc0[8], acc1[8];
#pragma unroll
            for (int p = 0; p < 8; p++) { acc0[p] = 0ull; acc1[p] = 0ull; }

            float2 wbuf[4];
#pragma unroll
            for (int i = 0; i < 4; i++) wbuf[i] = Wt2[i * 300 + tid];

#pragma unroll 4
            for (int k = 0; k < EMB; k++) {
                float2 w = wbuf[k & 3];
                if (k + 4 < EMB) wbuf[k & 3] = Wt2[(k + 4) * 300 + tid];
                ull w0 = pack2(w.x, w.x);
                ull w1 = pack2(w.y, w.y);
                ull h0v = h2s[k][0], h1v = h2s[k][1], h2v = h2s[k][2], h3v = h2s[k][3];
                ull h4v = h2s[k][4], h5v = h2s[k][5], h6v = h2s[k][6], h7v = h2s[k][7];
                acc0[0] = ffma2(h0v, w0, acc0[0]);  acc1[0] = ffma2(h0v, w1, acc1[0]);
                acc0[1] = ffma2(h1v, w0, acc0[1]);  acc1[1] = ffma2(h1v, w1, acc1[1]);
                acc0[2] = ffma2(h2v, w0, acc0[2]);  acc1[2] = ffma2(h2v, w1, acc1[2]);
                acc0[3] = ffma2(h3v, w0, acc0[3]);  acc1[3] = ffma2(h3v, w1, acc1[3]);
                acc0[4] = ffma2(h4v, w0, acc0[4]);  acc1[4] = ffma2(h4v, w1, acc1[4]);
                acc0[5] = ffma2(h5v, w0, acc0[5]);  acc1[5] = ffma2(h5v, w1, acc1[5]);
                acc0[6] = ffma2(h6v, w0, acc0[6]);  acc1[6] = ffma2(h6v, w1, acc1[6]);
                acc0[7] = ffma2(h7v, w0, acc0[7]);  acc1[7] = ffma2(h7v, w1, acc1[7]);
            }

            int c0 = 2 * tid, c1 = 2 * tid + 1;
            float2* g0 = reinterpret_cast<float2*>(&ghs[c0][0]);
            float2* g1 = reinterpret_cast<float2*>(&ghs[c1][0]);
#pragma unroll
            for (int p = 0; p < 8; p++) {
                g0[p] = unpack2(acc0[p]);
                g1[p] = unpack2(acc1[p]);
            }
        }
        __syncthreads();

        {
            const __half* gib = gih + ((size_t)t * BSZ + b0) * GDIM;
            __half* hout = hidh + ((size_t)(t + 1) * BSZ + b0) * EMB;
#pragma unroll
            for (int it = 0; it < (ROWS_PER * EMB) / SCAN_THREADS; it++) {
                int e = tid + it * SCAN_THREADS;
                int r = e / EMB, j = e - r * EMB;
                const __half* gr = gib + (size_t)r * GDIM;
                float gir = __half2float(gr[j]);
                float giz = __half2float(gr[j + 200]);
                float gin = __half2float(gr[j + 400]);
                float ghr = ghs[j][r]       + bhh_s[j];
                float ghz = ghs[j + 200][r] + bhh_s[j + 200];
                float ghn = ghs[j + 400][r] + bhh_s[j + 400];
                float rg = 1.f / (1.f + expf(-(gir + ghr)));
                float z  = 1.f / (1.f + expf(-(giz + ghz)));
                float n  = tanhf(gin + rg * ghn);
                float hold = hsf[j * 18 + r];
                float hnew = (1.f - z) * n + z * hold;
                hsf[j * 18 + r] = hnew;
                hout[(size_t)r * EMB + j] = __float2half(hnew);
            }
        }
        __syncthreads();
    }
}

// ---------------- 200 -> 12 projection ----------------
template <int MODE>
__global__ void proj_kernel(const float* __restrict__ H,
                            const float* __restrict__ W2,
                            const float* __restrict__ b2,
                            float* __restrict__ out, int M)
{
    int warp = (blockIdx.x * blockDim.x + threadIdx.x) >> 5;
    int lane = threadIdx.x & 31;
    if (warp >= M) return;
    const float* row = H + (size_t)warp * EMB;
    float acc[SDIM];
#pragma unroll
    for (int s = 0; s < SDIM; s++) acc[s] = 0.f;
    for (int k = lane; k < EMB; k += 32) {
        float hv = row[k];
#pragma unroll
        for (int s = 0; s < SDIM; s++)
            acc[s] = fmaf(hv, W2[s * EMB + k], acc[s]);
    }
#pragma unroll
    for (int s = 0; s < SDIM; s++) {
#pragma unroll
        for (int off = 16; off > 0; off >>= 1)
            acc[s] += __shfl_xor_sync(0xffffffffu, acc[s], off);
    }
    if (lane == 0) {
        float* o = out + (size_t)warp * SDIM;
#pragma unroll
        for (int s = 0; s < SDIM; s++) {
            float v = acc[s] + b2[s];
            if (MODE == 1) {
                float sp = log1pf(expf(-fabsf(v))) + fmaxf(v, 0.f);
                v = sqrtf(sp + EPSV);
            }
            o[s] = v;
        }
    }
}

// ---------------- host-side ----------------
static void launch_hm(int act, const __half* A, int lda, const __half* W, int ldw,
                      const float* bias, const float* base, int baseMask,
                      float* outF, int ldf, __half* outH, int ldh,
                      int M, int N, int K)
{
    dim3 grid((N + 127) / 128, M / 128);
    dim3 blk(256);
    if (base) {
        if (act == ACT_NONE)      hm_gemm<ACT_NONE, true><<<grid, blk>>>(A, lda, W, ldw, bias, base, baseMask, outF, ldf, outH, ldh, M, N, K);
        else if (act == ACT_RELU) hm_gemm<ACT_RELU, true><<<grid, blk>>>(A, lda, W, ldw, bias, base, baseMask, outF, ldf, outH, ldh, M, N, K);
        else                      hm_gemm<ACT_TANH, true><<<grid, blk>>>(A, lda, W, ldw, bias, base, baseMask, outF, ldf, outH, ldh, M, N, K);
    } else {
        if (act == ACT_NONE)      hm_gemm<ACT_NONE, false><<<grid, blk>>>(A, lda, W, ldw, bias, nullptr, 0, outF, ldf, outH, ldh, M, N, K);
        else if (act == ACT_RELU) hm_gemm<ACT_RELU, false><<<grid, blk>>>(A, lda, W, ldw, bias, nullptr, 0, outF, ldf, outH, ldh, M, N, K);
        else                      hm_gemm<ACT_TANH, false><<<grid, blk>>>(A, lda, W, ldw, bias, nullptr, 0, outF, ldf, outH, ldh, M, N, K);
    }
}

extern "C" void kernel_launch(void* const* d_in, const int* in_sizes, int n_in,
                              void* d_out, int out_size)
{
    const float* x        = (const float*)d_in[0];
    const float* u        = (const float*)d_in[1];
    const float* ctx_mean = (const float*)d_in[2];
    const float* lctx     = (const float*)d_in[3];
    const float* se_w1 = (const float*)d_in[4];  const float* se_b1 = (const float*)d_in[5];
    const float* se_w2 = (const float*)d_in[6];  const float* se_b2 = (const float*)d_in[7];
    const float* ae_w1 = (const float*)d_in[8];  const float* ae_b1 = (const float*)d_in[9];
    const float* ae_w2 = (const float*)d_in[10]; const float* ae_b2 = (const float*)d_in[11];
    const float* ce_w1 = (const float*)d_in[12]; const float* ce_b1 = (const float*)d_in[13];
    const float* ce_w2 = (const float*)d_in[14]; const float* ce_b2 = (const float*)d_in[15];
    const float* lce_w1 = (const float*)d_in[16]; const float* lce_b1 = (const float*)d_in[17];
    const float* lce_w2 = (const float*)d_in[18]; const float* lce_b2 = (const float*)d_in[19];
    const float* dec_w1 = (const float*)d_in[20]; const float* dec_b1 = (const float*)d_in[21];
    const float* dec_w2 = (const float*)d_in[22]; const float* dec_b2 = (const float*)d_in[23];
    const float* gru_wih = (const float*)d_in[24]; const float* gru_bih = (const float*)d_in[25];
    const float* gru_whh = (const float*)d_in[26]; const float* gru_bhh = (const float*)d_in[27];
    const float* cov_w1 = (const float*)d_in[28]; const float* cov_b1 = (const float*)d_in[29];
    const float* cov_w2 = (const float*)d_in[30]; const float* cov_b2 = (const float*)d_in[31];

    float  *p_gibase, *p_h0, *p_tmp, *p_wt;
    __half *p_h1h, *p_ctxh, *p_alch, *p_gih, *p_hidh, *p_wh;
    cudaGetSymbolAddress((void**)&p_gibase, g_gibase);
    cudaGetSymbolAddress((void**)&p_h0,     g_h0);
    cudaGetSymbolAddress((void**)&p_tmp,    g_tmp);
    cudaGetSymbolAddress((void**)&p_wt,     g_whh_t);
    cudaGetSymbolAddress((void**)&p_h1h,    g_h1h);
    cudaGetSymbolAddress((void**)&p_ctxh,   g_ctxh);
    cudaGetSymbolAddress((void**)&p_alch,   g_alch);
    cudaGetSymbolAddress((void**)&p_gih,    g_gih);
    cudaGetSymbolAddress((void**)&p_hidh,   g_hidh);
    cudaGetSymbolAddress((void**)&p_wh,     g_wh);

    cudaFuncSetAttribute(scan_kernel, cudaFuncAttributeMaxDynamicSharedMemorySize, SCAN_SMEM);

    float* out_mean = (float*)d_out;
    float* out_std  = out_mean + (size_t)MROWS * SDIM;

    const int eb = 256;

    // weights -> half (single kernel)
    conv_w_kernel<<<(360000 + eb - 1) / eb, eb>>>(se_w2, ce_w2, ae_w2, lce_w2,
                                                  dec_w1, cov_w1, gru_wih, p_wh);
    transpose_whh_kernel<<<(GDIM * EMB + eb - 1) / eb, eb>>>(gru_whh, p_wt);

    // state_embed -> h0 (fp32 for scan) + hidh block 0 (half for dec/cov)
    embed1_kernel<<<(BSZ * EMB + eb - 1) / eb, eb>>>(x, se_w1, se_b1, p_h1h, BSZ, SDIM);
    launch_hm(ACT_TANH, p_h1h, EMB, p_wh + WH_SE, EMB, se_b2, nullptr, 0,
              p_h0, EMB, p_hidh, EMB, BSZ, EMB, EMB);

    // ctx_embed (half), then gi_base (fp32)
    embed1_kernel<<<(BSZ * EMB + eb - 1) / eb, eb>>>(ctx_mean, ce_w1, ce_b1, p_h1h, BSZ, 8);
    launch_hm(ACT_RELU, p_h1h, EMB, p_wh + WH_CE, EMB, ce_b2, nullptr, 0,
              nullptr, 0, p_ctxh, EMB, BSZ, EMB, EMB);
    launch_hm(ACT_NONE, p_ctxh, EMB, p_wh + WH_WIH, GDIM, gru_bih, nullptr, 0,
              p_gibase, GDIM, nullptr, 0, BSZ, GDIM, EMB);

    // action embed (all T) -> alc[:, 0:200] (half)
    embed1_kernel<<<((size_t)MBIG * EMB + eb - 1) / eb, eb>>>(u, ae_w1, ae_b1, p_h1h, MBIG, 4);
    launch_hm(ACT_RELU, p_h1h, EMB, p_wh + WH_AE, EMB, ae_b2, nullptr, 0,
              nullptr, 0, p_alch, 400, MBIG, EMB, EMB);

    // local ctx embed -> alc[:, 200:400] (half)
    embed1_kernel<<<((size_t)MBIG * EMB + eb - 1) / eb, eb>>>(lctx, lce_w1, lce_b1, p_h1h, MBIG, 6);
    launch_hm(ACT_RELU, p_h1h, EMB, p_wh + WH_LCE, EMB, lce_b2, nullptr, 0,
              nullptr, 0, p_alch + 200, 400, MBIG, EMB, EMB);

    // gi = [a|lc] @ Wih[:,200:600]^T + gi_base  (half out)
    launch_hm(ACT_NONE, p_alch, 400, p_wh + WH_WIH + 200, GDIM, nullptr, p_gibase, BSZ - 1,
              nullptr, 0, p_gih, GDIM, MBIG, GDIM, 400);

    // fused persistent GRU scan (reads half gi, writes half hiddens)
    scan_kernel<<<SCAN_CTAS, SCAN_THREADS, SCAN_SMEM>>>(p_wt, gru_bhh, p_gih, p_h0, p_hidh);

    // decode mean
    launch_hm(ACT_RELU, p_hidh, EMB, p_wh + WH_DEC, EMB, dec_b1, nullptr, 0,
              p_tmp, EMB, nullptr, 0, MROWS, EMB, EMB);
    {
        int blocks = (MROWS * 32 + 255) / 256;
        proj_kernel<0><<<blocks, 256>>>(p_tmp, dec_w2, dec_b2, out_mean, MROWS);
    }
    // cov -> std
    launch_hm(ACT_RELU, p_hidh, EMB, p_wh + WH_COV, EMB, cov_b1, nullptr, 0,
              p_tmp, EMB, nullptr, 0, MROWS, EMB, EMB);
    {
        int blocks = (MROWS * 32 + 255) / 256;
        proj_kernel<1><<<blocks, 256>>>(p_tmp, cov_w2, cov_b2, out_std, MROWS);
    }

    (void)in_sizes; (void)n_in; (void)out_size;
}

// round 8
// speedup vs baseline: 2.7984x; 1.0374x over previous
#include <cuda_runtime.h>
#include <cuda_fp16.h>
#include <cstdint>

// ---------------- problem dims ----------------
#define BSZ   2048
#define TST   100
#define EMB   200
#define SDIM  12
#define GDIM  600            // 3*EMB
#define MBIG  (TST*BSZ)      // 204800 rows
#define MROWS ((TST+1)*BSZ)  // 206848 rows
#define EPSV  1e-4f

typedef unsigned long long ull;

__device__ __forceinline__ ull ffma2(ull a, ull b, ull c) {
    ull d;
    asm("fma.rn.f32x2 %0, %1, %2, %3;" : "=l"(d) : "l"(a), "l"(b), "l"(c));
    return d;
}
__device__ __forceinline__ ull pack2(float lo, float hi) {
    ull d;
    asm("mov.b64 %0, {%1, %2};" : "=l"(d) : "f"(lo), "f"(hi));
    return d;
}
__device__ __forceinline__ float2 unpack2(ull v) {
    float2 r;
    asm("mov.b64 {%0, %1}, %2;" : "=f"(r.x), "=f"(r.y) : "l"(v));
    return r;
}
__device__ __forceinline__ uint32_t smem_u32(const void* p) {
    uint32_t a;
    asm("{ .reg .u64 t; cvta.to.shared.u64 t, %1; cvt.u32.u64 %0, t; }" : "=r"(a) : "l"(p));
    return a;
}

// mma.sync m16n8k16 f16 -> f32 accum
__device__ __forceinline__ void mma_f16(float c[4],
                                        uint32_t a0, uint32_t a1, uint32_t a2, uint32_t a3,
                                        uint32_t b0, uint32_t b1) {
    asm volatile(
        "mma.sync.aligned.m16n8k16.row.col.f32.f16.f16.f32 "
        "{%0,%1,%2,%3}, {%4,%5,%6,%7}, {%8,%9}, {%0,%1,%2,%3};"
        : "+f"(c[0]), "+f"(c[1]), "+f"(c[2]), "+f"(c[3])
        : "r"(a0), "r"(a1), "r"(a2), "r"(a3), "r"(b0), "r"(b1));
}

__device__ __forceinline__ void ldsm_x4(uint32_t& r0, uint32_t& r1, uint32_t& r2, uint32_t& r3,
                                        uint32_t addr) {
    asm volatile("ldmatrix.sync.aligned.m8n8.x4.shared.b16 {%0,%1,%2,%3}, [%4];"
                 : "=r"(r0), "=r"(r1), "=r"(r2), "=r"(r3) : "r"(addr));
}

__device__ __forceinline__ void cp16h(uint32_t daddr, const __half* src, uint32_t bytes) {
    asm volatile("cp.async.ca.shared.global [%0], [%1], 16, %2;"
                 :: "r"(daddr), "l"(src), "r"(bytes));
}
#define CP_COMMIT()  asm volatile("cp.async.commit_group;" ::: "memory")
#define CP_WAIT_1()  asm volatile("cp.async.wait_group 1;" ::: "memory")
#define CP_WAIT_0()  asm volatile("cp.async.wait_group 0;" ::: "memory")

// ---------------- device scratch ----------------
__device__ __align__(128) float  g_gibase[BSZ * GDIM];
__device__ __align__(128) float  g_h0[BSZ * EMB];
__device__ __align__(128) float  g_tmp[(size_t)MROWS * EMB];
__device__ __align__(128) float  g_whh_t[EMB * GDIM];
__device__ __align__(128) __half g_h1h[(size_t)MBIG * EMB];
__device__ __align__(128) __half g_ctxh[BSZ * EMB];
__device__ __align__(128) __half g_alch[(size_t)MBIG * 400];
__device__ __align__(128) __half g_gih[(size_t)MBIG * GDIM];
__device__ __align__(128) __half g_hidh[(size_t)MROWS * EMB];
__device__ __align__(128) __half g_wh[600000];

#define WH_SE   0
#define WH_CE   40000
#define WH_AE   80000
#define WH_LCE  120000
#define WH_DEC  160000
#define WH_COV  200000
#define WH_WIH  240000   // 600x600

// ---------------- fp16 tensor-core GEMM (K chunk 64, ldmatrix, cp.async db) ----------------
// smem per tile: 128 rows x 72 halves (144 B/row); per buffer: A tile + B tile.
#define ROWB      144                 // bytes per smem row
#define TILE_B    (128 * ROWB)        // 18432
#define BUF_B     (2 * TILE_B)        // 36864
#define HM_SMEM   (2 * BUF_B)         // 73728

enum { ACT_NONE = 0, ACT_RELU = 1, ACT_TANH = 2 };

// stage [128 rows x 64 halves]: 1024 16B-slots, 256 threads x 4 passes
__device__ __forceinline__ void stage_h64(uint32_t sbase, const __half* __restrict__ src,
                                          int ld, int row0, int rowsValid,
                                          int k0, int K, int tid)
{
#pragma unroll
    for (int pass = 0; pass < 4; pass++) {
        int e = tid + pass * 256;
        int r = e >> 3, c = e & 7;
        int ks = k0 + c * 8;
        int valid = (r < rowsValid) ? min(max((K - ks) * 2, 0), 16) : 0;
        const __half* g = src + (size_t)(row0 + ((r < rowsValid) ? r : 0)) * ld + (valid ? ks : 0);
        cp16h(sbase + (uint32_t)(r * ROWB + c * 16), g, (uint32_t)valid);
    }
}

template <int ACT, bool HAS_BASE>
__global__ void __launch_bounds__(256, 2)
hm_gemm(const __half* __restrict__ A, int lda,
        const __half* __restrict__ W, int ldw,
        const float* __restrict__ bias,
        const float* __restrict__ base, int baseMask,
        float* __restrict__ outF, int ldf,
        __half* __restrict__ outH, int ldh,
        int M, int N, int K)
{
    extern __shared__ char smh[];
    const uint32_t smem_base = smem_u32(smh);

    const int tid  = threadIdx.x;
    const int wid  = tid >> 5;
    const int lane = tid & 31;
    const int warp_m = wid >> 1;       // 0..3 -> 32 rows
    const int warp_n = wid & 1;        // 0..1 -> 64 cols
    const int bm = blockIdx.y * 128;
    const int bn = blockIdx.x * 128;
    const int nValid = min(128, N - bn);

    const int lg = lane >> 2;          // 0..7
    const int lt = lane & 3;           // 0..3

    // ldmatrix per-lane offsets (bytes within tile)
    const uint32_t aRow = (uint32_t)(warp_m * 32 + (lane & 15));
    const uint32_t aOff = aRow * ROWB + ((lane >> 4) << 3) * 2;          // +8 halves if lane>=16
    const uint32_t bRow = (uint32_t)(warp_n * 64 + ((lane >> 4) & 1) * 8 + (lane & 7));
    const uint32_t bOff = bRow * ROWB + (((lane >> 3) & 1) << 3) * 2;    // +8 halves for k8 group

    float acc[2][8][4];
#pragma unroll
    for (int mt = 0; mt < 2; mt++)
#pragma unroll
        for (int nt = 0; nt < 8; nt++)
#pragma unroll
            for (int j = 0; j < 4; j++) acc[mt][nt][j] = 0.f;

    const int nk = (K + 63) / 64;

    stage_h64(smem_base,          A, lda, bm, 128,    0, K, tid);
    stage_h64(smem_base + TILE_B, W, ldw, bn, nValid, 0, K, tid);
    CP_COMMIT();

    for (int kc = 0; kc < nk; kc++) {
        if (kc + 1 < nk) {
            uint32_t nb = smem_base + (uint32_t)(((kc + 1) & 1) * BUF_B);
            int k0n = (kc + 1) * 64;
            stage_h64(nb,          A, lda, bm, 128,    k0n, K, tid);
            stage_h64(nb + TILE_B, W, ldw, bn, nValid, k0n, K, tid);
            CP_COMMIT();
            CP_WAIT_1();
        } else {
            CP_WAIT_0();
        }
        __syncthreads();

        const uint32_t aBase = smem_base + (uint32_t)((kc & 1) * BUF_B) + aOff;
        const uint32_t bBase = smem_base + (uint32_t)((kc & 1) * BUF_B) + TILE_B + bOff;

#pragma unroll
        for (int kk = 0; kk < 4; kk++) {
            const uint32_t kByte = (uint32_t)(kk * 32);   // 16 halves
            uint32_t af[2][4];
            ldsm_x4(af[0][0], af[0][1], af[0][2], af[0][3], aBase + kByte);
            ldsm_x4(af[1][0], af[1][1], af[1][2], af[1][3], aBase + 16 * ROWB + kByte);
#pragma unroll
            for (int p = 0; p < 4; p++) {
                uint32_t b00, b01, b10, b11;
                ldsm_x4(b00, b01, b10, b11, bBase + (uint32_t)(p * 16 * ROWB) + kByte);
                mma_f16(acc[0][2 * p],     af[0][0], af[0][1], af[0][2], af[0][3], b00, b01);
                mma_f16(acc[1][2 * p],     af[1][0], af[1][1], af[1][2], af[1][3], b00, b01);
                mma_f16(acc[0][2 * p + 1], af[0][0], af[0][1], af[0][2], af[0][3], b10, b11);
                mma_f16(acc[1][2 * p + 1], af[1][0], af[1][1], af[1][2], af[1][3], b10, b11);
            }
        }
        __syncthreads();
    }

    // epilogue
#pragma unroll
    for (int mt = 0; mt < 2; mt++) {
        int gm0 = bm + warp_m * 32 + mt * 16 + lg;       // rows gm0, gm0+8
        const float* base0 = HAS_BASE ? (base + (size_t)(gm0 & baseMask) * GDIM) : nullptr;
        const float* base1 = HAS_BASE ? (base + (size_t)((gm0 + 8) & baseMask) * GDIM) : nullptr;
#pragma unroll
        for (int nt = 0; nt < 8; nt++) {
            int gnl = warp_n * 64 + nt * 8 + lt * 2;
            if (gnl >= nValid) continue;
            int gn = bn + gnl;
            float b0v = bias ? bias[gn]     : 0.f;
            float b1v = bias ? bias[gn + 1] : 0.f;
            float v00 = acc[mt][nt][0] + b0v;
            float v01 = acc[mt][nt][1] + b1v;
            float v10 = acc[mt][nt][2] + b0v;
            float v11 = acc[mt][nt][3] + b1v;
            if (HAS_BASE) {
                v00 += base0[gn]; v01 += base0[gn + 1];
                v10 += base1[gn]; v11 += base1[gn + 1];
            }
            if (ACT == ACT_RELU) {
                v00 = fmaxf(v00, 0.f); v01 = fmaxf(v01, 0.f);
                v10 = fmaxf(v10, 0.f); v11 = fmaxf(v11, 0.f);
            } else if (ACT == ACT_TANH) {
                v00 = tanhf(v00); v01 = tanhf(v01);
                v10 = tanhf(v10); v11 = tanhf(v11);
            }
            if (outF) {
                *reinterpret_cast<float2*>(outF + (size_t)gm0 * ldf + gn)       = make_float2(v00, v01);
                *reinterpret_cast<float2*>(outF + (size_t)(gm0 + 8) * ldf + gn) = make_float2(v10, v11);
            }
            if (outH) {
                *reinterpret_cast<__half2*>(outH + (size_t)gm0 * ldh + gn)       = __floats2half2_rn(v00, v01);
                *reinterpret_cast<__half2*>(outH + (size_t)(gm0 + 8) * ldh + gn) = __floats2half2_rn(v10, v11);
            }
        }
    }
}

// ---------------- tiny-K first layer (half output) ----------------
__global__ void embed1_kernel(const float* __restrict__ X,
                              const float* __restrict__ W,
                              const float* __restrict__ B,
                              __half* __restrict__ Y, int M, int K)
{
    int idx = blockIdx.x * blockDim.x + threadIdx.x;
    if (idx >= M * EMB) return;
    int m = idx / EMB, j = idx - m * EMB;
    const float* xr = X + (size_t)m * K;
    const float* wr = W + (size_t)j * K;
    float s = B[j];
    for (int k = 0; k < K; k++) s = fmaf(xr[k], wr[k], s);
    Y[idx] = __float2half(fmaxf(s, 0.f));
}

// ---------------- convert all GEMM weights to half ----------------
__global__ void conv_w_kernel(const float* __restrict__ se, const float* __restrict__ ce,
                              const float* __restrict__ ae, const float* __restrict__ lce,
                              const float* __restrict__ dec, const float* __restrict__ cov,
                              const float* __restrict__ wih, __half* __restrict__ wh)
{
    int i = blockIdx.x * blockDim.x + threadIdx.x;
    if (i < 40000) {
        wh[WH_SE  + i] = __float2half(se[i]);
        wh[WH_CE  + i] = __float2half(ce[i]);
        wh[WH_AE  + i] = __float2half(ae[i]);
        wh[WH_LCE + i] = __float2half(lce[i]);
        wh[WH_DEC + i] = __float2half(dec[i]);
        wh[WH_COV + i] = __float2half(cov[i]);
    }
    if (i < 360000) wh[WH_WIH + i] = __float2half(wih[i]);
}

// ---------------- Whh transpose ----------------
__global__ void transpose_whh_kernel(const float* __restrict__ W,
                                     float* __restrict__ Wt)
{
    int idx = blockIdx.x * blockDim.x + threadIdx.x;
    if (idx >= GDIM * EMB) return;
    int c = idx / EMB, k = idx - c * EMB;
    Wt[k * GDIM + c] = W[idx];
}

// ---------------- persistent fused GRU scan ----------------
#define SCAN_CTAS    128
#define ROWS_PER     16
#define SCAN_THREADS 320
#define H2S_BYTES    (200 * 9 * 8)
#define GHS_BYTES    (600 * 18 * 4)
#define SCAN_SMEM    (H2S_BYTES + GHS_BYTES + 600 * 4)

__global__ void __launch_bounds__(SCAN_THREADS, 1)
scan_kernel(const float* __restrict__ Wt,
            const float* __restrict__ bhh,
            const __half* __restrict__ gih,
            const float* __restrict__ h0,
            __half* __restrict__ hidh)
{
    extern __shared__ char sm[];
    ull   (*h2s)[9]  = reinterpret_cast<ull(*)[9]>(sm);
    float (*ghs)[18] = reinterpret_cast<float(*)[18]>(sm + H2S_BYTES);
    float* bhh_s     = reinterpret_cast<float*>(sm + H2S_BYTES + GHS_BYTES);
    float* hsf       = reinterpret_cast<float*>(sm);

    const int tid = threadIdx.x;
    const int b0  = blockIdx.x * ROWS_PER;
    const float2* Wt2 = reinterpret_cast<const float2*>(Wt);

    for (int j = tid; j < GDIM; j += SCAN_THREADS) bhh_s[j] = bhh[j];
    for (int e = tid; e < ROWS_PER * EMB; e += SCAN_THREADS) {
        int r = e / EMB, j = e - r * EMB;
        hsf[j * 18 + r] = h0[(size_t)(b0 + r) * EMB + j];
    }
    __syncthreads();

    const bool active = (tid < 300);

    for (int t = 0; t < TST; t++) {
        if (active) {
            ull acc0[8], acc1[8];
#pragma unroll
            for (int p = 0; p < 8; p++) { acc0[p] = 0ull; acc1[p] = 0ull; }

            float2 wbuf[4];
#pragma unroll
            for (int i = 0; i < 4; i++) wbuf[i] = Wt2[i * 300 + tid];

#pragma unroll 4
            for (int k = 0; k < EMB; k++) {
                float2 w = wbuf[k & 3];
                if (k + 4 < EMB) wbuf[k & 3] = Wt2[(k + 4) * 300 + tid];
                ull w0 = pack2(w.x, w.x);
                ull w1 = pack2(w.y, w.y);
                ull h0v = h2s[k][0], h1v = h2s[k][1], h2v = h2s[k][2], h3v = h2s[k][3];
                ull h4v = h2s[k][4], h5v = h2s[k][5], h6v = h2s[k][6], h7v = h2s[k][7];
                acc0[0] = ffma2(h0v, w0, acc0[0]);  acc1[0] = ffma2(h0v, w1, acc1[0]);
                acc0[1] = ffma2(h1v, w0, acc0[1]);  acc1[1] = ffma2(h1v, w1, acc1[1]);
                acc0[2] = ffma2(h2v, w0, acc0[2]);  acc1[2] = ffma2(h2v, w1, acc1[2]);
                acc0[3] = ffma2(h3v, w0, acc0[3]);  acc1[3] = ffma2(h3v, w1, acc1[3]);
                acc0[4] = ffma2(h4v, w0, acc0[4]);  acc1[4] = ffma2(h4v, w1, acc1[4]);
                acc0[5] = ffma2(h5v, w0, acc0[5]);  acc1[5] = ffma2(h5v, w1, acc1[5]);
                acc0[6] = ffma2(h6v, w0, acc0[6]);  acc1[6] = ffma2(h6v, w1, acc1[6]);
                acc0[7] = ffma2(h7v, w0, acc0[7]);  acc1[7] = ffma2(h7v, w1, acc1[7]);
            }

            int c0 = 2 * tid, c1 = 2 * tid + 1;
            float2* g0 = reinterpret_cast<float2*>(&ghs[c0][0]);
            float2* g1 = reinterpret_cast<float2*>(&ghs[c1][0]);
#pragma unroll
            for (int p = 0; p < 8; p++) {
                g0[p] = unpack2(acc0[p]);
                g1[p] = unpack2(acc1[p]);
            }
        }
        __syncthreads();

        {
            const __half* gib = gih + ((size_t)t * BSZ + b0) * GDIM;
            __half* hout = hidh + ((size_t)(t + 1) * BSZ + b0) * EMB;
#pragma unroll
            for (int it = 0; it < (ROWS_PER * EMB) / SCAN_THREADS; it++) {
                int e = tid + it * SCAN_THREADS;
                int r = e / EMB, j = e - r * EMB;
                const __half* gr = gib + (size_t)r * GDIM;
                float gir = __half2float(gr[j]);
                float giz = __half2float(gr[j + 200]);
                float gin = __half2float(gr[j + 400]);
                float ghr = ghs[j][r]       + bhh_s[j];
                float ghz = ghs[j + 200][r] + bhh_s[j + 200];
                float ghn = ghs[j + 400][r] + bhh_s[j + 400];
                float rg = 1.f / (1.f + expf(-(gir + ghr)));
                float z  = 1.f / (1.f + expf(-(giz + ghz)));
                float n  = tanhf(gin + rg * ghn);
                float hold = hsf[j * 18 + r];
                float hnew = (1.f - z) * n + z * hold;
                hsf[j * 18 + r] = hnew;
                hout[(size_t)r * EMB + j] = __float2half(hnew);
            }
        }
        __syncthreads();
    }
}

// ---------------- 200 -> 12 projection ----------------
template <int MODE>
__global__ void proj_kernel(const float* __restrict__ H,
                            const float* __restrict__ W2,
                            const float* __restrict__ b2,
                            float* __restrict__ out, int M)
{
    int warp = (blockIdx.x * blockDim.x + threadIdx.x) >> 5;
    int lane = threadIdx.x & 31;
    if (warp >= M) return;
    const float* row = H + (size_t)warp * EMB;
    float acc[SDIM];
#pragma unroll
    for (int s = 0; s < SDIM; s++) acc[s] = 0.f;
    for (int k = lane; k < EMB; k += 32) {
        float hv = row[k];
#pragma unroll
        for (int s = 0; s < SDIM; s++)
            acc[s] = fmaf(hv, W2[s * EMB + k], acc[s]);
    }
#pragma unroll
    for (int s = 0; s < SDIM; s++) {
#pragma unroll
        for (int off = 16; off > 0; off >>= 1)
            acc[s] += __shfl_xor_sync(0xffffffffu, acc[s], off);
    }
    if (lane == 0) {
        float* o = out + (size_t)warp * SDIM;
#pragma unroll
        for (int s = 0; s < SDIM; s++) {
            float v = acc[s] + b2[s];
            if (MODE == 1) {
                float sp = log1pf(expf(-fabsf(v))) + fmaxf(v, 0.f);
                v = sqrtf(sp + EPSV);
            }
            o[s] = v;
        }
    }
}

// ---------------- host-side ----------------
static void launch_hm(int act, const __half* A, int lda, const __half* W, int ldw,
                      const float* bias, const float* base, int baseMask,
                      float* outF, int ldf, __half* outH, int ldh,
                      int M, int N, int K)
{
    dim3 grid((N + 127) / 128, M / 128);
    dim3 blk(256);
    size_t shm = HM_SMEM;
    if (base) {
        if (act == ACT_NONE)      hm_gemm<ACT_NONE, true><<<grid, blk, shm>>>(A, lda, W, ldw, bias, base, baseMask, outF, ldf, outH, ldh, M, N, K);
        else if (act == ACT_RELU) hm_gemm<ACT_RELU, true><<<grid, blk, shm>>>(A, lda, W, ldw, bias, base, baseMask, outF, ldf, outH, ldh, M, N, K);
        else                      hm_gemm<ACT_TANH, true><<<grid, blk, shm>>>(A, lda, W, ldw, bias, base, baseMask, outF, ldf, outH, ldh, M, N, K);
    } else {
        if (act == ACT_NONE)      hm_gemm<ACT_NONE, false><<<grid, blk, shm>>>(A, lda, W, ldw, bias, nullptr, 0, outF, ldf, outH, ldh, M, N, K);
        else if (act == ACT_RELU) hm_gemm<ACT_RELU, false><<<grid, blk, shm>>>(A, lda, W, ldw, bias, nullptr, 0, outF, ldf, outH, ldh, M, N, K);
        else                      hm_gemm<ACT_TANH, false><<<grid, blk, shm>>>(A, lda, W, ldw, bias, nullptr, 0, outF, ldf, outH, ldh, M, N, K);
    }
}

extern "C" void kernel_launch(void* const* d_in, const int* in_sizes, int n_in,
                              void* d_out, int out_size)
{
    const float* x        = (const float*)d_in[0];
    const float* u        = (const float*)d_in[1];
    const float* ctx_mean = (const float*)d_in[2];
    const float* lctx     = (const float*)d_in[3];
    const float* se_w1 = (const float*)d_in[4];  const float* se_b1 = (const float*)d_in[5];
    const float* se_w2 = (const float*)d_in[6];  const float* se_b2 = (const float*)d_in[7];
    const float* ae_w1 = (const float*)d_in[8];  const float* ae_b1 = (const float*)d_in[9];
    const float* ae_w2 = (const float*)d_in[10]; const float* ae_b2 = (const float*)d_in[11];
    const float* ce_w1 = (const float*)d_in[12]; const float* ce_b1 = (const float*)d_in[13];
    const float* ce_w2 = (const float*)d_in[14]; const float* ce_b2 = (const float*)d_in[15];
    const float* lce_w1 = (const float*)d_in[16]; const float* lce_b1 = (const float*)d_in[17];
    const float* lce_w2 = (const float*)d_in[18]; const float* lce_b2 = (const float*)d_in[19];
    const float* dec_w1 = (const float*)d_in[20]; const float* dec_b1 = (const float*)d_in[21];
    const float* dec_w2 = (const float*)d_in[22]; const float* dec_b2 = (const float*)d_in[23];
    const float* gru_wih = (const float*)d_in[24]; const float* gru_bih = (const float*)d_in[25];
    const float* gru_whh = (const float*)d_in[26]; const float* gru_bhh = (const float*)d_in[27];
    const float* cov_w1 = (const float*)d_in[28]; const float* cov_b1 = (const float*)d_in[29];
    const float* cov_w2 = (const float*)d_in[30]; const float* cov_b2 = (const float*)d_in[31];

    float  *p_gibase, *p_h0, *p_tmp, *p_wt;
    __half *p_h1h, *p_ctxh, *p_alch, *p_gih, *p_hidh, *p_wh;
    cudaGetSymbolAddress((void**)&p_gibase, g_gibase);
    cudaGetSymbolAddress((void**)&p_h0,     g_h0);
    cudaGetSymbolAddress((void**)&p_tmp,    g_tmp);
    cudaGetSymbolAddress((void**)&p_wt,     g_whh_t);
    cudaGetSymbolAddress((void**)&p_h1h,    g_h1h);
    cudaGetSymbolAddress((void**)&p_ctxh,   g_ctxh);
    cudaGetSymbolAddress((void**)&p_alch,   g_alch);
    cudaGetSymbolAddress((void**)&p_gih,    g_gih);
    cudaGetSymbolAddress((void**)&p_hidh,   g_hidh);
    cudaGetSymbolAddress((void**)&p_wh,     g_wh);

    cudaFuncSetAttribute(scan_kernel, cudaFuncAttributeMaxDynamicSharedMemorySize, SCAN_SMEM);
    cudaFuncSetAttribute(hm_gemm<ACT_NONE, true>,  cudaFuncAttributeMaxDynamicSharedMemorySize, HM_SMEM);
    cudaFuncSetAttribute(hm_gemm<ACT_RELU, true>,  cudaFuncAttributeMaxDynamicSharedMemorySize, HM_SMEM);
    cudaFuncSetAttribute(hm_gemm<ACT_TANH, true>,  cudaFuncAttributeMaxDynamicSharedMemorySize, HM_SMEM);
    cudaFuncSetAttribute(hm_gemm<ACT_NONE, false>, cudaFuncAttributeMaxDynamicSharedMemorySize, HM_SMEM);
    cudaFuncSetAttribute(hm_gemm<ACT_RELU, false>, cudaFuncAttributeMaxDynamicSharedMemorySize, HM_SMEM);
    cudaFuncSetAttribute(hm_gemm<ACT_TANH, false>, cudaFuncAttributeMaxDynamicSharedMemorySize, HM_SMEM);

    float* out_mean = (float*)d_out;
    float* out_std  = out_mean + (size_t)MROWS * SDIM;

    const int eb = 256;

    conv_w_kernel<<<(360000 + eb - 1) / eb, eb>>>(se_w2, ce_w2, ae_w2, lce_w2,
                                                  dec_w1, cov_w1, gru_wih, p_wh);
    transpose_whh_kernel<<<(GDIM * EMB + eb - 1) / eb, eb>>>(gru_whh, p_wt);

    // state_embed -> h0 (fp32 for scan) + hidh block 0 (half for dec/cov)
    embed1_kernel<<<(BSZ * EMB + eb - 1) / eb, eb>>>(x, se_w1, se_b1, p_h1h, BSZ, SDIM);
    launch_hm(ACT_TANH, p_h1h, EMB, p_wh + WH_SE, EMB, se_b2, nullptr, 0,
              p_h0, EMB, p_hidh, EMB, BSZ, EMB, EMB);

    // ctx_embed (half), then gi_base (fp32)
    embed1_kernel<<<(BSZ * EMB + eb - 1) / eb, eb>>>(ctx_mean, ce_w1, ce_b1, p_h1h, BSZ, 8);
    launch_hm(ACT_RELU, p_h1h, EMB, p_wh + WH_CE, EMB, ce_b2, nullptr, 0,
              nullptr, 0, p_ctxh, EMB, BSZ, EMB, EMB);
    launch_hm(ACT_NONE, p_ctxh, EMB, p_wh + WH_WIH, GDIM, gru_bih, nullptr, 0,
              p_gibase, GDIM, nullptr, 0, BSZ, GDIM, EMB);

    // action embed (all T) -> alc[:, 0:200] (half)
    embed1_kernel<<<((size_t)MBIG * EMB + eb - 1) / eb, eb>>>(u, ae_w1, ae_b1, p_h1h, MBIG, 4);
    launch_hm(ACT_RELU, p_h1h, EMB, p_wh + WH_AE, EMB, ae_b2, nullptr, 0,
              nullptr, 0, p_alch, 400, MBIG, EMB, EMB);

    // local ctx embed -> alc[:, 200:400] (half)
    embed1_kernel<<<((size_t)MBIG * EMB + eb - 1) / eb, eb>>>(lctx, lce_w1, lce_b1, p_h1h, MBIG, 6);
    launch_hm(ACT_RELU, p_h1h, EMB, p_wh + WH_LCE, EMB, lce_b2, nullptr, 0,
              nullptr, 0, p_alch + 200, 400, MBIG, EMB, EMB);

    // gi = [a|lc] @ Wih[:,200:600]^T + gi_base  (half out)
    launch_hm(ACT_NONE, p_alch, 400, p_wh + WH_WIH + 200, GDIM, nullptr, p_gibase, BSZ - 1,
              nullptr, 0, p_gih, GDIM, MBIG, GDIM, 400);

    // fused persistent GRU scan
    scan_kernel<<<SCAN_CTAS, SCAN_THREADS, SCAN_SMEM>>>(p_wt, gru_bhh, p_gih, p_h0, p_hidh);

    // decode mean
    launch_hm(ACT_RELU, p_hidh, EMB, p_wh + WH_DEC, EMB, dec_b1, nullptr, 0,
              p_tmp, EMB, nullptr, 0, MROWS, EMB, EMB);
    {
        int blocks = (MROWS * 32 + 255) / 256;
        proj_kernel<0><<<blocks, 256>>>(p_tmp, dec_w2, dec_b2, out_mean, MROWS);
    }
    // cov -> std
    launch_hm(ACT_RELU, p_hidh, EMB, p_wh + WH_COV, EMB, cov_b1, nullptr, 0,
              p_tmp, EMB, nullptr, 0, MROWS, EMB, EMB);
    {
        int blocks = (MROWS * 32 + 255) / 256;
        proj_kernel<1><<<blocks, 256>>>(p_tmp, cov_w2, cov_b2, out_std, MROWS);
    }

    (void)in_sizes; (void)n_in; (void)out_size;
}